// round 2
// baseline (speedup 1.0000x reference)
#include <cuda_runtime.h>
#include <math.h>

#define NN 50000
#define EE 800000
#define HIDC 128
#define FFC 256
#define NLAYERS 6
#define EPSLN 1e-5f

// ---------------- scratch (device globals; no allocation allowed) ----------------
__device__ float g_z[NN * HIDC];
__device__ float g_q[NN * HIDC];
__device__ float g_k[NN * HIDC];
__device__ float g_v[NN * HIDC];
__device__ float g_sk[NN * HIDC];
__device__ float g_attn[NN * HIDC];
__device__ float g_h[NN * HIDC];
__device__ float g_t[NN * FFC];
__device__ float g_u[NN * HIDC];
__device__ float g_score[EE * 2];
__device__ float g_denom[NN * 2];
__device__ unsigned g_smax[NN * 2];
__device__ int g_src[EE];
__device__ int g_dst[EE];
__device__ float g_betas[NLAYERS + 2];
__device__ int g_flag[1];

// ---------------- helpers ----------------
__device__ __forceinline__ unsigned fenc(float f) {
    unsigned u = __float_as_uint(f);
    return (u & 0x80000000u) ? ~u : (u | 0x80000000u);
}
__device__ __forceinline__ float fdec(unsigned k) {
    return (k & 0x80000000u) ? __uint_as_float(k ^ 0x80000000u)
                             : __uint_as_float(~k);
}

// ---------------- edge index dtype sniff + convert ----------------
__global__ void sniff_kernel(const unsigned* __restrict__ w) {
    if (threadIdx.x == 0 && blockIdx.x == 0) {
        int is64 = 1;
        for (int i = 1; i < 64; i += 2)
            if (w[i] != 0u) { is64 = 0; break; }
        g_flag[0] = is64;
    }
}

__global__ __launch_bounds__(256) void convert_edges(const void* __restrict__ ei) {
    int e = blockIdx.x * blockDim.x + threadIdx.x;
    if (e >= EE) return;
    if (g_flag[0]) {
        const long long* p = (const long long*)ei;
        g_src[e] = (int)p[e];
        g_dst[e] = (int)p[EE + e];
    } else {
        const int* p = (const int*)ei;
        g_src[e] = p[e];
        g_dst[e] = p[EE + e];
    }
}

__global__ void beta_softmax(const float* __restrict__ beta) {
    if (threadIdx.x == 0 && blockIdx.x == 0) {
        float m = -1e30f;
        for (int i = 0; i < NLAYERS + 1; i++) m = fmaxf(m, beta[i]);
        float s = 0.f;
        for (int i = 0; i < NLAYERS + 1; i++) {
            float e = expf(beta[i] - m);
            g_betas[i] = e;
            s += e;
        }
        for (int i = 0; i < NLAYERS + 1; i++) g_betas[i] /= s;
    }
}

// one fused clear: attn [NN*HIDC], denom [NN*2], smax [NN*2]
__global__ __launch_bounds__(256) void clear_layer() {
    int i = blockIdx.x * blockDim.x + threadIdx.x;
    if (i < NN * HIDC) g_attn[i] = 0.f;
    if (i < NN * 2) {
        g_denom[i] = 0.f;
        g_smax[i] = 0u;
    }
}

// ---------------- GEMM: C[M,Nld] = act(A[M,K] @ B[K,Nld] + bias) ----------------
// tile 64(M) x 128(N), K chunks of 64, 256 threads, 4x8 accum per thread.
#define TILE_M 64
#define KCH 64

template <int ACT>
__global__ __launch_bounds__(256) void gemm_bias(
    const float* __restrict__ A, const float* __restrict__ B,
    const float* __restrict__ bias, float* __restrict__ C,
    int M, int K, int Nld) {
    __shared__ float As[TILE_M][KCH];     // 16 KB
    __shared__ float Bs[KCH][128];        // 32 KB   (total 48 KB)

    int m0 = blockIdx.x * TILE_M;
    int n0 = blockIdx.y * 128;
    int tid = threadIdx.x;
    int tx = tid & 15, ty = tid >> 4;

    float acc[4][8];
#pragma unroll
    for (int r = 0; r < 4; r++)
#pragma unroll
        for (int c = 0; c < 8; c++) acc[r][c] = 0.f;

    for (int kc = 0; kc < K; kc += KCH) {
        // load A tile (64x64 floats = 1024 float4, 4 per thread)
#pragma unroll
        for (int i = 0; i < 4; i++) {
            int f = tid + i * 256;
            int row = f >> 4;
            int c4 = (f & 15) * 4;
            float4 av = make_float4(0.f, 0.f, 0.f, 0.f);
            if (m0 + row < M)
                av = *(const float4*)(A + (size_t)(m0 + row) * K + kc + c4);
            *(float4*)&As[row][c4] = av;
        }
        // load B tile (64x128 floats = 2048 float4, 8 per thread)
#pragma unroll
        for (int i = 0; i < 8; i++) {
            int f = tid + i * 256;
            int row = f >> 5;
            int c4 = (f & 31) * 4;
            *(float4*)&Bs[row][c4] =
                *(const float4*)(B + (size_t)(kc + row) * Nld + n0 + c4);
        }
        __syncthreads();
#pragma unroll 8
        for (int kk = 0; kk < KCH; kk++) {
            float a0 = As[ty * 4 + 0][kk];
            float a1 = As[ty * 4 + 1][kk];
            float a2 = As[ty * 4 + 2][kk];
            float a3 = As[ty * 4 + 3][kk];
            float4 b0 = *(const float4*)&Bs[kk][tx * 4];
            float4 b1 = *(const float4*)&Bs[kk][64 + tx * 4];
            float bv[8] = {b0.x, b0.y, b0.z, b0.w, b1.x, b1.y, b1.z, b1.w};
            float av[4] = {a0, a1, a2, a3};
#pragma unroll
            for (int r = 0; r < 4; r++)
#pragma unroll
                for (int c = 0; c < 8; c++) acc[r][c] += av[r] * bv[c];
        }
        __syncthreads();
    }

#pragma unroll
    for (int r = 0; r < 4; r++) {
        int row = m0 + ty * 4 + r;
        if (row >= M) continue;
#pragma unroll
        for (int half = 0; half < 2; half++) {
            float4 o;
            float* po = (float*)&o;
#pragma unroll
            for (int c = 0; c < 4; c++) {
                int col = n0 + half * 64 + tx * 4 + c;
                float vv = acc[r][half * 4 + c] + bias[col];
                if (ACT == 1) vv = fmaxf(vv, 0.f);
                if (ACT == 2) vv = 0.5f * vv * (1.f + erff(vv * 0.70710678118654752f));
                po[c] = vv;
            }
            *(float4*)(C + (size_t)row * Nld + n0 + half * 64 + tx * 4) = o;
        }
    }
}

// ---------------- attention edge kernels ----------------
// warp per edge: score[e,h] = dot(q[dst],k[src]) per 64-wide head / 8
__global__ __launch_bounds__(256) void edge_score() {
    int e = (blockIdx.x * blockDim.x + threadIdx.x) >> 5;
    if (e >= EE) return;
    int lane = threadIdx.x & 31;
    int s = g_src[e], d = g_dst[e];
    float4 qv = *(const float4*)(g_q + (size_t)d * HIDC + lane * 4);
    float4 kv = *(const float4*)(g_k + (size_t)s * HIDC + lane * 4);
    float p = qv.x * kv.x + qv.y * kv.y + qv.z * kv.z + qv.w * kv.w;
#pragma unroll
    for (int off = 8; off > 0; off >>= 1)
        p += __shfl_down_sync(0xffffffffu, p, off, 16);
    if ((lane & 15) == 0) {
        int h = lane >> 4;
        float sc = p * 0.125f;  // 1/sqrt(64)
        g_score[(size_t)e * 2 + h] = sc;
        atomicMax(&g_smax[(size_t)d * 2 + h], fenc(sc));
    }
}

__global__ __launch_bounds__(256) void edge_alpha() {
    int i = blockIdx.x * blockDim.x + threadIdx.x;
    if (i >= EE * 2) return;
    int e = i >> 1, h = i & 1;
    int d = g_dst[e];
    float m = fdec(g_smax[(size_t)d * 2 + h]);
    float a = expf(g_score[i] - m);
    g_score[i] = a;
    atomicAdd(&g_denom[(size_t)d * 2 + h], a);
}

__global__ __launch_bounds__(256) void edge_msg() {
    int e = (blockIdx.x * blockDim.x + threadIdx.x) >> 5;
    if (e >= EE) return;
    int lane = threadIdx.x & 31;
    int h = lane >> 4;
    int s = g_src[e], d = g_dst[e];
    float w = g_score[(size_t)e * 2 + h] / g_denom[(size_t)d * 2 + h];
    float4 vv = *(const float4*)(g_v + (size_t)s * HIDC + lane * 4);
    float* base = g_attn + (size_t)d * HIDC + lane * 4;
    atomicAdd(base + 0, w * vv.x);
    atomicAdd(base + 1, w * vv.y);
    atomicAdd(base + 2, w * vv.z);
    atomicAdd(base + 3, w * vv.w);
}

// ---------------- layernorm kernels (warp per row, 128 cols) ----------------
__global__ __launch_bounds__(256) void ln3_kernel(
    const float* __restrict__ g, const float* __restrict__ bt) {
    int row = (blockIdx.x * blockDim.x + threadIdx.x) >> 5;
    if (row >= NN) return;
    int lane = threadIdx.x & 31;
    size_t base = (size_t)row * HIDC + lane * 4;
    float4 a = *(const float4*)(g_z + base);
    float4 b = *(const float4*)(g_attn + base);
    float4 c = *(const float4*)(g_sk + base);
    float v0 = a.x + b.x + c.x, v1 = a.y + b.y + c.y;
    float v2 = a.z + b.z + c.z, v3 = a.w + b.w + c.w;
    float s = v0 + v1 + v2 + v3;
#pragma unroll
    for (int o = 16; o > 0; o >>= 1) s += __shfl_xor_sync(0xffffffffu, s, o);
    float mu = s * (1.f / HIDC);
    float d0 = v0 - mu, d1 = v1 - mu, d2 = v2 - mu, d3 = v3 - mu;
    float ss = d0 * d0 + d1 * d1 + d2 * d2 + d3 * d3;
#pragma unroll
    for (int o = 16; o > 0; o >>= 1) ss += __shfl_xor_sync(0xffffffffu, ss, o);
    float rs = rsqrtf(ss * (1.f / HIDC) + EPSLN);
    int col = lane * 4;
    float4 o4;
    o4.x = d0 * rs * g[col + 0] + bt[col + 0];
    o4.y = d1 * rs * g[col + 1] + bt[col + 1];
    o4.z = d2 * rs * g[col + 2] + bt[col + 2];
    o4.w = d3 * rs * g[col + 3] + bt[col + 3];
    *(float4*)(g_h + base) = o4;
}

// z = relu(LN(h+u)); out += betas[li]*z
__global__ __launch_bounds__(256) void lnacc_kernel(
    const float* __restrict__ g, const float* __restrict__ bt,
    float* __restrict__ out, int li) {
    int row = (blockIdx.x * blockDim.x + threadIdx.x) >> 5;
    if (row >= NN) return;
    int lane = threadIdx.x & 31;
    size_t base = (size_t)row * HIDC + lane * 4;
    float4 a = *(const float4*)(g_h + base);
    float4 b = *(const float4*)(g_u + base);
    float v0 = a.x + b.x, v1 = a.y + b.y, v2 = a.z + b.z, v3 = a.w + b.w;
    float s = v0 + v1 + v2 + v3;
#pragma unroll
    for (int o = 16; o > 0; o >>= 1) s += __shfl_xor_sync(0xffffffffu, s, o);
    float mu = s * (1.f / HIDC);
    float d0 = v0 - mu, d1 = v1 - mu, d2 = v2 - mu, d3 = v3 - mu;
    float ss = d0 * d0 + d1 * d1 + d2 * d2 + d3 * d3;
#pragma unroll
    for (int o = 16; o > 0; o >>= 1) ss += __shfl_xor_sync(0xffffffffu, ss, o);
    float rs = rsqrtf(ss * (1.f / HIDC) + EPSLN);
    int col = lane * 4;
    float z0 = fmaxf(d0 * rs * g[col + 0] + bt[col + 0], 0.f);
    float z1 = fmaxf(d1 * rs * g[col + 1] + bt[col + 1], 0.f);
    float z2 = fmaxf(d2 * rs * g[col + 2] + bt[col + 2], 0.f);
    float z3 = fmaxf(d3 * rs * g[col + 3] + bt[col + 3], 0.f);
    float bb = g_betas[li];
    float4 zn = make_float4(z0, z1, z2, z3);
    *(float4*)(g_z + base) = zn;
    float4 oo = *(float4*)(out + base);
    oo.x += bb * z0; oo.y += bb * z1; oo.z += bb * z2; oo.w += bb * z3;
    *(float4*)(out + base) = oo;
}

__global__ __launch_bounds__(256) void init_acc(float* __restrict__ out) {
    int i = blockIdx.x * blockDim.x + threadIdx.x;
    if (i < NN * HIDC) out[i] = g_betas[0] * g_z[i];
}

// ---------------- host launcher ----------------
extern "C" void kernel_launch(void* const* d_in, const int* in_sizes, int n_in,
                              void* d_out, int out_size) {
    const float* x    = (const float*)d_in[0];
    const void*  ei   = d_in[1];
    const float* Win  = (const float*)d_in[2];
    const float* b_in = (const float*)d_in[3];
    const float* Wq   = (const float*)d_in[4];
    const float* bq   = (const float*)d_in[5];
    const float* Wk   = (const float*)d_in[6];
    const float* bk   = (const float*)d_in[7];
    const float* Wv   = (const float*)d_in[8];
    const float* bv   = (const float*)d_in[9];
    const float* Wsk  = (const float*)d_in[10];
    const float* bsk  = (const float*)d_in[11];
    const float* W1   = (const float*)d_in[12];
    const float* b1   = (const float*)d_in[13];
    const float* W2   = (const float*)d_in[14];
    const float* b2   = (const float*)d_in[15];
    const float* g1   = (const float*)d_in[16];
    const float* bt1  = (const float*)d_in[17];
    const float* g2   = (const float*)d_in[18];
    const float* bt2  = (const float*)d_in[19];
    const float* beta = (const float*)d_in[20];
    float* out = (float*)d_out;

    float *z, *q, *k, *v, *sk, *h, *t, *u;
    cudaGetSymbolAddress((void**)&z, g_z);
    cudaGetSymbolAddress((void**)&q, g_q);
    cudaGetSymbolAddress((void**)&k, g_k);
    cudaGetSymbolAddress((void**)&v, g_v);
    cudaGetSymbolAddress((void**)&sk, g_sk);
    cudaGetSymbolAddress((void**)&h, g_h);
    cudaGetSymbolAddress((void**)&t, g_t);
    cudaGetSymbolAddress((void**)&u, g_u);

    const int GM = (NN + TILE_M - 1) / TILE_M;  // 782

    sniff_kernel<<<1, 32>>>((const unsigned*)ei);
    convert_edges<<<(EE + 255) / 256, 256>>>(ei);
    beta_softmax<<<1, 32>>>(beta);

    // z = relu(x @ Win + b_in)
    gemm_bias<1><<<dim3(GM, 1), 256>>>(x, Win, b_in, z, NN, HIDC, HIDC);
    init_acc<<<(NN * HIDC + 255) / 256, 256>>>(out);

    for (int l = 0; l < NLAYERS; l++) {
        size_t wo = (size_t)l * HIDC * HIDC;
        gemm_bias<0><<<dim3(GM, 1), 256>>>(z, Wq + wo, bq + l * HIDC, q, NN, HIDC, HIDC);
        gemm_bias<0><<<dim3(GM, 1), 256>>>(z, Wk + wo, bk + l * HIDC, k, NN, HIDC, HIDC);
        gemm_bias<0><<<dim3(GM, 1), 256>>>(z, Wv + wo, bv + l * HIDC, v, NN, HIDC, HIDC);
        gemm_bias<0><<<dim3(GM, 1), 256>>>(z, Wsk + wo, bsk + l * HIDC, sk, NN, HIDC, HIDC);

        clear_layer<<<(NN * HIDC + 255) / 256, 256>>>();

        edge_score<<<(EE + 7) / 8, 256>>>();
        edge_alpha<<<(EE * 2 + 255) / 256, 256>>>();
        edge_msg<<<(EE + 7) / 8, 256>>>();

        ln3_kernel<<<(NN + 7) / 8, 256>>>(g1 + l * HIDC, bt1 + l * HIDC);

        gemm_bias<2><<<dim3(GM, 2), 256>>>(h, W1 + (size_t)l * HIDC * FFC,
                                           b1 + l * FFC, t, NN, HIDC, FFC);
        gemm_bias<0><<<dim3(GM, 1), 256>>>(t, W2 + (size_t)l * FFC * HIDC,
                                           b2 + l * HIDC, u, NN, FFC, HIDC);

        lnacc_kernel<<<(NN + 7) / 8, 256>>>(g2 + l * HIDC, bt2 + l * HIDC, out, l + 1);
    }
}

// round 4
// speedup vs baseline: 2.6201x; 2.6201x over previous
#include <cuda_runtime.h>
#include <math.h>
#include <stdint.h>

#define NN 50000
#define EE 800000
#define HIDC 128
#define FFC 256
#define NLAYERS 6
#define EPSLN 1e-5f

// ---------------- scratch (device globals; no allocation allowed) ----------------
__device__ float g_z[NN * HIDC];
__device__ float g_q[NN * HIDC];
__device__ float g_k[NN * HIDC];
__device__ float g_v[NN * HIDC];
__device__ float g_sk[NN * HIDC];
__device__ float g_attn[NN * HIDC];
__device__ float g_h[NN * HIDC];
__device__ float g_t[NN * FFC];
__device__ float g_u[NN * HIDC];
__device__ int g_src[EE];
__device__ int g_dst[EE];
__device__ int g_deg[NN];
__device__ int g_rowptr[NN + 1];
__device__ int g_cur[NN];
__device__ int g_csrc[EE];
__device__ int g_csums[128];
__device__ float g_betas[NLAYERS + 2];
__device__ int g_flag[1];

#define CHUNK 512
#define NCHK ((NN + CHUNK - 1) / CHUNK)   // 98

// ---------------- edge index dtype sniff + convert ----------------
__global__ void sniff_kernel(const unsigned* __restrict__ w) {
    if (threadIdx.x == 0 && blockIdx.x == 0) {
        int is64 = 1;
        for (int i = 1; i < 64; i += 2)
            if (w[i] != 0u) { is64 = 0; break; }
        g_flag[0] = is64;
    }
}

__global__ __launch_bounds__(256) void convert_edges(const void* __restrict__ ei) {
    int e = blockIdx.x * blockDim.x + threadIdx.x;
    if (e >= EE) return;
    if (g_flag[0]) {
        const long long* p = (const long long*)ei;
        g_src[e] = (int)p[e];
        g_dst[e] = (int)p[EE + e];
    } else {
        const int* p = (const int*)ei;
        g_src[e] = p[e];
        g_dst[e] = p[EE + e];
    }
}

__global__ void beta_softmax(const float* __restrict__ beta) {
    if (threadIdx.x == 0 && blockIdx.x == 0) {
        float m = -1e30f;
        for (int i = 0; i < NLAYERS + 1; i++) m = fmaxf(m, beta[i]);
        float s = 0.f;
        for (int i = 0; i < NLAYERS + 1; i++) {
            float e = expf(beta[i] - m);
            g_betas[i] = e;
            s += e;
        }
        for (int i = 0; i < NLAYERS + 1; i++) g_betas[i] /= s;
    }
}

// ---------------- CSR build ----------------
__global__ __launch_bounds__(256) void k_clear_deg() {
    int i = blockIdx.x * blockDim.x + threadIdx.x;
    if (i < NN) g_deg[i] = 0;
}
__global__ __launch_bounds__(256) void k_hist() {
    int e = blockIdx.x * blockDim.x + threadIdx.x;
    if (e < EE) atomicAdd(&g_deg[g_dst[e]], 1);
}
__global__ __launch_bounds__(CHUNK) void k_chunksum() {
    __shared__ int sh[CHUNK];
    int tid = threadIdx.x;
    int i = blockIdx.x * CHUNK + tid;
    sh[tid] = (i < NN) ? g_deg[i] : 0;
    __syncthreads();
    for (int off = CHUNK / 2; off > 0; off >>= 1) {
        if (tid < off) sh[tid] += sh[tid + off];
        __syncthreads();
    }
    if (tid == 0) g_csums[blockIdx.x] = sh[0];
}
__global__ void k_scanchunks() {
    if (threadIdx.x == 0 && blockIdx.x == 0) {
        int run = 0;
        for (int c = 0; c < NCHK; c++) {
            int v = g_csums[c];
            g_csums[c] = run;
            run += v;
        }
        g_rowptr[NN] = run;
    }
}
__global__ __launch_bounds__(CHUNK) void k_rowptr() {
    __shared__ int sh[CHUNK];
    int tid = threadIdx.x;
    int i = blockIdx.x * CHUNK + tid;
    int v = (i < NN) ? g_deg[i] : 0;
    sh[tid] = v;
    __syncthreads();
    for (int off = 1; off < CHUNK; off <<= 1) {
        int t = (tid >= off) ? sh[tid - off] : 0;
        __syncthreads();
        sh[tid] += t;
        __syncthreads();
    }
    if (i < NN) {
        int excl = sh[tid] - v + g_csums[blockIdx.x];
        g_rowptr[i] = excl;
        g_cur[i] = excl;
    }
}
__global__ __launch_bounds__(256) void k_fill() {
    int e = blockIdx.x * blockDim.x + threadIdx.x;
    if (e >= EE) return;
    int slot = atomicAdd(&g_cur[g_dst[e]], 1);
    g_csrc[slot] = g_src[e];
}

// ---------------- TF32 tensor-core GEMM ----------------
// C[M,Nld] = act(A[M,K] @ B[K,Nld] + bias)
// block 128x128, 128 threads (4 warps, 2x2), warp tile 64x64, BK=32.
#define BM 128
#define BN 128
#define BK 32

__device__ __forceinline__ uint32_t f2tf32(float x) {
    uint32_t r;
    asm("cvt.rna.tf32.f32 %0, %1;" : "=r"(r) : "f"(x));
    return r;
}

__device__ __forceinline__ void mma_tf32(float* d, const uint32_t* a, const uint32_t* b) {
    asm volatile(
        "mma.sync.aligned.m16n8k8.row.col.f32.tf32.tf32.f32 "
        "{%0,%1,%2,%3}, {%4,%5,%6,%7}, {%8,%9}, {%0,%1,%2,%3};"
        : "+f"(d[0]), "+f"(d[1]), "+f"(d[2]), "+f"(d[3])
        : "r"(a[0]), "r"(a[1]), "r"(a[2]), "r"(a[3]), "r"(b[0]), "r"(b[1]));
}

template <int ACT>
__global__ __launch_bounds__(128) void gemm_tf32(
    const float* __restrict__ A, const float* __restrict__ B,
    const float* __restrict__ bias, float* __restrict__ C,
    int M, int K, int Nld) {
    __shared__ __align__(16) float As[BM][BK + 4];   // pad 4 -> frag LDS conflict-free
    __shared__ __align__(16) float Bs[BK][BN + 8];   // pad 8 -> frag LDS conflict-free

    int m0 = blockIdx.x * BM;
    int n0 = blockIdx.y * BN;
    int tid = threadIdx.x;
    int warp = tid >> 5, lane = tid & 31;
    int wm = (warp >> 1) * 64, wn = (warp & 1) * 64;
    int g = lane >> 2, t = lane & 3;

    float acc[4][8][4];
#pragma unroll
    for (int a = 0; a < 4; a++)
#pragma unroll
        for (int b = 0; b < 8; b++)
#pragma unroll
            for (int c = 0; c < 4; c++) acc[a][b][c] = 0.f;

    for (int kc = 0; kc < K; kc += BK) {
        // stage A (128x32): 1024 float4 / 128 thr = 8 each, convert to tf32
#pragma unroll
        for (int i = 0; i < 8; i++) {
            int f = tid + i * 128;
            int m = f >> 3;
            int k4 = (f & 7) * 4;
            float4 av = make_float4(0.f, 0.f, 0.f, 0.f);
            if (m0 + m < M)
                av = *(const float4*)(A + (size_t)(m0 + m) * K + kc + k4);
            float4 cv;
            cv.x = __uint_as_float(f2tf32(av.x));
            cv.y = __uint_as_float(f2tf32(av.y));
            cv.z = __uint_as_float(f2tf32(av.z));
            cv.w = __uint_as_float(f2tf32(av.w));
            *(float4*)&As[m][k4] = cv;
        }
        // stage B (32x128): 1024 float4 / 128 thr = 8 each
#pragma unroll
        for (int i = 0; i < 8; i++) {
            int f = tid + i * 128;
            int k = f >> 5;
            int n4 = (f & 31) * 4;
            float4 bv = *(const float4*)(B + (size_t)(kc + k) * Nld + n0 + n4);
            float4 cv;
            cv.x = __uint_as_float(f2tf32(bv.x));
            cv.y = __uint_as_float(f2tf32(bv.y));
            cv.z = __uint_as_float(f2tf32(bv.z));
            cv.w = __uint_as_float(f2tf32(bv.w));
            *(float4*)&Bs[k][n4] = cv;
        }
        __syncthreads();

#pragma unroll
        for (int kk = 0; kk < BK; kk += 8) {
            uint32_t af[4][4];
#pragma unroll
            for (int tm = 0; tm < 4; tm++) {
                int mb = wm + tm * 16;
                af[tm][0] = __float_as_uint(As[mb + g][kk + t]);
                af[tm][1] = __float_as_uint(As[mb + g + 8][kk + t]);
                af[tm][2] = __float_as_uint(As[mb + g][kk + t + 4]);
                af[tm][3] = __float_as_uint(As[mb + g + 8][kk + t + 4]);
            }
            uint32_t bf[8][2];
#pragma unroll
            for (int tn = 0; tn < 8; tn++) {
                int nb = wn + tn * 8;
                bf[tn][0] = __float_as_uint(Bs[kk + t][nb + g]);
                bf[tn][1] = __float_as_uint(Bs[kk + t + 4][nb + g]);
            }
#pragma unroll
            for (int tm = 0; tm < 4; tm++)
#pragma unroll
                for (int tn = 0; tn < 8; tn++)
                    mma_tf32(acc[tm][tn], af[tm], bf[tn]);
        }
        __syncthreads();
    }

    // epilogue: c0,c1 row g col 2t,2t+1 ; c2,c3 row g+8
#pragma unroll
    for (int tm = 0; tm < 4; tm++) {
        int r0 = m0 + wm + tm * 16 + g;
        int r1 = r0 + 8;
#pragma unroll
        for (int tn = 0; tn < 8; tn++) {
            int cb = n0 + wn + tn * 8 + 2 * t;
            float b0 = __ldg(bias + cb);
            float b1 = __ldg(bias + cb + 1);
            float v00 = acc[tm][tn][0] + b0;
            float v01 = acc[tm][tn][1] + b1;
            float v10 = acc[tm][tn][2] + b0;
            float v11 = acc[tm][tn][3] + b1;
            if (ACT == 1) {
                v00 = fmaxf(v00, 0.f); v01 = fmaxf(v01, 0.f);
                v10 = fmaxf(v10, 0.f); v11 = fmaxf(v11, 0.f);
            }
            if (ACT == 2) {
                v00 = 0.5f * v00 * (1.f + erff(v00 * 0.70710678118654752f));
                v01 = 0.5f * v01 * (1.f + erff(v01 * 0.70710678118654752f));
                v10 = 0.5f * v10 * (1.f + erff(v10 * 0.70710678118654752f));
                v11 = 0.5f * v11 * (1.f + erff(v11 * 0.70710678118654752f));
            }
            if (r0 < M) *(float2*)(C + (size_t)r0 * Nld + cb) = make_float2(v00, v01);
            if (r1 < M) *(float2*)(C + (size_t)r1 * Nld + cb) = make_float2(v10, v11);
        }
    }
}

// ---------------- fused attention: warp per dst node, online softmax ----------------
__global__ __launch_bounds__(256) void attn_fused() {
    int node = (blockIdx.x * blockDim.x + threadIdx.x) >> 5;
    if (node >= NN) return;
    int lane = threadIdx.x & 31;
    int beg = g_rowptr[node], end = g_rowptr[node + 1];
    size_t qb = (size_t)node * HIDC + lane * 4;
    float4 qv = *(const float4*)(g_q + qb);
    float m = -INFINITY, l = 0.f;
    float4 acc = make_float4(0.f, 0.f, 0.f, 0.f);
    for (int e = beg; e < end; e++) {
        int s = g_csrc[e];
        size_t sb = (size_t)s * HIDC + lane * 4;
        float4 kv = *(const float4*)(g_k + sb);
        float4 vv = *(const float4*)(g_v + sb);
        float p = qv.x * kv.x + qv.y * kv.y + qv.z * kv.z + qv.w * kv.w;
        p += __shfl_xor_sync(0xffffffffu, p, 8, 16);
        p += __shfl_xor_sync(0xffffffffu, p, 4, 16);
        p += __shfl_xor_sync(0xffffffffu, p, 2, 16);
        p += __shfl_xor_sync(0xffffffffu, p, 1, 16);
        float sc = p * 0.125f;  // 1/sqrt(64)
        float mn = fmaxf(m, sc);
        float scale = __expf(m - mn);
        float w = __expf(sc - mn);
        l = l * scale + w;
        acc.x = acc.x * scale + w * vv.x;
        acc.y = acc.y * scale + w * vv.y;
        acc.z = acc.z * scale + w * vv.z;
        acc.w = acc.w * scale + w * vv.w;
        m = mn;
    }
    float inv = (l > 0.f) ? 1.f / l : 0.f;
    acc.x *= inv; acc.y *= inv; acc.z *= inv; acc.w *= inv;
    *(float4*)(g_attn + qb) = acc;
}

// ---------------- layernorm kernels (warp per row, 128 cols) ----------------
__global__ __launch_bounds__(256) void ln3_kernel(
    const float* __restrict__ g, const float* __restrict__ bt) {
    int row = (blockIdx.x * blockDim.x + threadIdx.x) >> 5;
    if (row >= NN) return;
    int lane = threadIdx.x & 31;
    size_t base = (size_t)row * HIDC + lane * 4;
    float4 a = *(const float4*)(g_z + base);
    float4 b = *(const float4*)(g_attn + base);
    float4 c = *(const float4*)(g_sk + base);
    float v0 = a.x + b.x + c.x, v1 = a.y + b.y + c.y;
    float v2 = a.z + b.z + c.z, v3 = a.w + b.w + c.w;
    float s = v0 + v1 + v2 + v3;
#pragma unroll
    for (int o = 16; o > 0; o >>= 1) s += __shfl_xor_sync(0xffffffffu, s, o);
    float mu = s * (1.f / HIDC);
    float d0 = v0 - mu, d1 = v1 - mu, d2 = v2 - mu, d3 = v3 - mu;
    float ss = d0 * d0 + d1 * d1 + d2 * d2 + d3 * d3;
#pragma unroll
    for (int o = 16; o > 0; o >>= 1) ss += __shfl_xor_sync(0xffffffffu, ss, o);
    float rs = rsqrtf(ss * (1.f / HIDC) + EPSLN);
    int col = lane * 4;
    float4 o4;
    o4.x = d0 * rs * g[col + 0] + bt[col + 0];
    o4.y = d1 * rs * g[col + 1] + bt[col + 1];
    o4.z = d2 * rs * g[col + 2] + bt[col + 2];
    o4.w = d3 * rs * g[col + 3] + bt[col + 3];
    *(float4*)(g_h + base) = o4;
}

// z = relu(LN(h+u)); out += betas[li]*z
__global__ __launch_bounds__(256) void lnacc_kernel(
    const float* __restrict__ g, const float* __restrict__ bt,
    float* __restrict__ out, int li) {
    int row = (blockIdx.x * blockDim.x + threadIdx.x) >> 5;
    if (row >= NN) return;
    int lane = threadIdx.x & 31;
    size_t base = (size_t)row * HIDC + lane * 4;
    float4 a = *(const float4*)(g_h + base);
    float4 b = *(const float4*)(g_u + base);
    float v0 = a.x + b.x, v1 = a.y + b.y, v2 = a.z + b.z, v3 = a.w + b.w;
    float s = v0 + v1 + v2 + v3;
#pragma unroll
    for (int o = 16; o > 0; o >>= 1) s += __shfl_xor_sync(0xffffffffu, s, o);
    float mu = s * (1.f / HIDC);
    float d0 = v0 - mu, d1 = v1 - mu, d2 = v2 - mu, d3 = v3 - mu;
    float ss = d0 * d0 + d1 * d1 + d2 * d2 + d3 * d3;
#pragma unroll
    for (int o = 16; o > 0; o >>= 1) ss += __shfl_xor_sync(0xffffffffu, ss, o);
    float rs = rsqrtf(ss * (1.f / HIDC) + EPSLN);
    int col = lane * 4;
    float z0 = fmaxf(d0 * rs * g[col + 0] + bt[col + 0], 0.f);
    float z1 = fmaxf(d1 * rs * g[col + 1] + bt[col + 1], 0.f);
    float z2 = fmaxf(d2 * rs * g[col + 2] + bt[col + 2], 0.f);
    float z3 = fmaxf(d3 * rs * g[col + 3] + bt[col + 3], 0.f);
    float bb = g_betas[li];
    *(float4*)(g_z + base) = make_float4(z0, z1, z2, z3);
    float4 oo = *(float4*)(out + base);
    oo.x += bb * z0; oo.y += bb * z1; oo.z += bb * z2; oo.w += bb * z3;
    *(float4*)(out + base) = oo;
}

__global__ __launch_bounds__(256) void init_acc(float* __restrict__ out) {
    int i = blockIdx.x * blockDim.x + threadIdx.x;
    if (i < NN * HIDC) out[i] = g_betas[0] * g_z[i];
}

// ---------------- host launcher ----------------
extern "C" void kernel_launch(void* const* d_in, const int* in_sizes, int n_in,
                              void* d_out, int out_size) {
    const float* x    = (const float*)d_in[0];
    const void*  ei   = d_in[1];
    const float* Win  = (const float*)d_in[2];
    const float* b_in = (const float*)d_in[3];
    const float* Wq   = (const float*)d_in[4];
    const float* bq   = (const float*)d_in[5];
    const float* Wk   = (const float*)d_in[6];
    const float* bk   = (const float*)d_in[7];
    const float* Wv   = (const float*)d_in[8];
    const float* bv   = (const float*)d_in[9];
    const float* Wsk  = (const float*)d_in[10];
    const float* bsk  = (const float*)d_in[11];
    const float* W1   = (const float*)d_in[12];
    const float* b1   = (const float*)d_in[13];
    const float* W2   = (const float*)d_in[14];
    const float* b2   = (const float*)d_in[15];
    const float* g1   = (const float*)d_in[16];
    const float* bt1  = (const float*)d_in[17];
    const float* g2   = (const float*)d_in[18];
    const float* bt2  = (const float*)d_in[19];
    const float* beta = (const float*)d_in[20];
    float* out = (float*)d_out;

    float *z, *q, *k, *v, *sk, *h, *t, *u;
    cudaGetSymbolAddress((void**)&z, g_z);
    cudaGetSymbolAddress((void**)&q, g_q);
    cudaGetSymbolAddress((void**)&k, g_k);
    cudaGetSymbolAddress((void**)&v, g_v);
    cudaGetSymbolAddress((void**)&sk, g_sk);
    cudaGetSymbolAddress((void**)&h, g_h);
    cudaGetSymbolAddress((void**)&t, g_t);
    cudaGetSymbolAddress((void**)&u, g_u);

    const int GM = (NN + BM - 1) / BM;  // 391

    sniff_kernel<<<1, 32>>>((const unsigned*)ei);
    convert_edges<<<(EE + 255) / 256, 256>>>(ei);
    beta_softmax<<<1, 32>>>(beta);

    // CSR build (once; graph is static across layers)
    k_clear_deg<<<(NN + 255) / 256, 256>>>();
    k_hist<<<(EE + 255) / 256, 256>>>();
    k_chunksum<<<NCHK, CHUNK>>>();
    k_scanchunks<<<1, 32>>>();
    k_rowptr<<<NCHK, CHUNK>>>();
    k_fill<<<(EE + 255) / 256, 256>>>();

    // z = relu(x @ Win + b_in)
    gemm_tf32<1><<<dim3(GM, 1), 128>>>(x, Win, b_in, z, NN, HIDC, HIDC);
    init_acc<<<(NN * HIDC + 255) / 256, 256>>>(out);

    for (int l = 0; l < NLAYERS; l++) {
        size_t wo = (size_t)l * HIDC * HIDC;
        gemm_tf32<0><<<dim3(GM, 1), 128>>>(z, Wq + wo, bq + l * HIDC, q, NN, HIDC, HIDC);
        gemm_tf32<0><<<dim3(GM, 1), 128>>>(z, Wk + wo, bk + l * HIDC, k, NN, HIDC, HIDC);
        gemm_tf32<0><<<dim3(GM, 1), 128>>>(z, Wv + wo, bv + l * HIDC, v, NN, HIDC, HIDC);
        gemm_tf32<0><<<dim3(GM, 1), 128>>>(z, Wsk + wo, bsk + l * HIDC, sk, NN, HIDC, HIDC);

        attn_fused<<<(NN * 32 + 255) / 256, 256>>>();

        ln3_kernel<<<(NN + 7) / 8, 256>>>(g1 + l * HIDC, bt1 + l * HIDC);

        gemm_tf32<2><<<dim3(GM, 2), 128>>>(h, W1 + (size_t)l * HIDC * FFC,
                                           b1 + l * FFC, t, NN, HIDC, FFC);
        gemm_tf32<0><<<dim3(GM, 1), 128>>>(t, W2 + (size_t)l * FFC * HIDC,
                                           b2 + l * HIDC, u, NN, FFC, HIDC);

        lnacc_kernel<<<(NN + 7) / 8, 256>>>(g2 + l * HIDC, bt2 + l * HIDC, out, l + 1);
    }
}

// round 5
// speedup vs baseline: 2.8235x; 1.0776x over previous
#include <cuda_runtime.h>
#include <math.h>
#include <stdint.h>

#define NN 50000
#define EE 800000
#define HIDC 128
#define FFC 256
#define NLAYERS 6
#define EPSLN 1e-5f

// ---------------- scratch (device globals; no allocation allowed) ----------------
__device__ float g_z[NN * HIDC];
__device__ float g_q[NN * HIDC];
__device__ float g_k[NN * HIDC];
__device__ float g_v[NN * HIDC];
__device__ float g_sk[NN * HIDC];
__device__ float g_attn[NN * HIDC];
__device__ float g_h[NN * HIDC];
__device__ float g_t[NN * FFC];
__device__ float g_u[NN * HIDC];
__device__ int g_src[EE];
__device__ int g_dst[EE];
__device__ int g_deg[NN];
__device__ int g_rowptr[NN + 1];
__device__ int g_cur[NN];
__device__ int g_csrc[EE];
__device__ int g_csums[128];
__device__ float g_betas[NLAYERS + 2];
__device__ int g_flag[1];

#define CHUNK 512
#define NCHK ((NN + CHUNK - 1) / CHUNK)   // 98

// ---------------- edge index dtype sniff + convert ----------------
__global__ void sniff_kernel(const unsigned* __restrict__ w) {
    if (threadIdx.x == 0 && blockIdx.x == 0) {
        int is64 = 1;
        for (int i = 1; i < 64; i += 2)
            if (w[i] != 0u) { is64 = 0; break; }
        g_flag[0] = is64;
    }
}

__global__ __launch_bounds__(256) void convert_edges(const void* __restrict__ ei) {
    int e = blockIdx.x * blockDim.x + threadIdx.x;
    if (e >= EE) return;
    if (g_flag[0]) {
        const long long* p = (const long long*)ei;
        g_src[e] = (int)p[e];
        g_dst[e] = (int)p[EE + e];
    } else {
        const int* p = (const int*)ei;
        g_src[e] = p[e];
        g_dst[e] = p[EE + e];
    }
}

__global__ void beta_softmax(const float* __restrict__ beta) {
    if (threadIdx.x == 0 && blockIdx.x == 0) {
        float m = -1e30f;
        for (int i = 0; i < NLAYERS + 1; i++) m = fmaxf(m, beta[i]);
        float s = 0.f;
        for (int i = 0; i < NLAYERS + 1; i++) {
            float e = expf(beta[i] - m);
            g_betas[i] = e;
            s += e;
        }
        for (int i = 0; i < NLAYERS + 1; i++) g_betas[i] /= s;
    }
}

// ---------------- CSR build ----------------
__global__ __launch_bounds__(256) void k_clear_deg() {
    int i = blockIdx.x * blockDim.x + threadIdx.x;
    if (i < NN) g_deg[i] = 0;
}
__global__ __launch_bounds__(256) void k_hist() {
    int e = blockIdx.x * blockDim.x + threadIdx.x;
    if (e < EE) atomicAdd(&g_deg[g_dst[e]], 1);
}
__global__ __launch_bounds__(CHUNK) void k_chunksum() {
    __shared__ int sh[CHUNK];
    int tid = threadIdx.x;
    int i = blockIdx.x * CHUNK + tid;
    sh[tid] = (i < NN) ? g_deg[i] : 0;
    __syncthreads();
    for (int off = CHUNK / 2; off > 0; off >>= 1) {
        if (tid < off) sh[tid] += sh[tid + off];
        __syncthreads();
    }
    if (tid == 0) g_csums[blockIdx.x] = sh[0];
}
__global__ void k_scanchunks() {
    if (threadIdx.x == 0 && blockIdx.x == 0) {
        int run = 0;
        for (int c = 0; c < NCHK; c++) {
            int v = g_csums[c];
            g_csums[c] = run;
            run += v;
        }
        g_rowptr[NN] = run;
    }
}
__global__ __launch_bounds__(CHUNK) void k_rowptr() {
    __shared__ int sh[CHUNK];
    int tid = threadIdx.x;
    int i = blockIdx.x * CHUNK + tid;
    int v = (i < NN) ? g_deg[i] : 0;
    sh[tid] = v;
    __syncthreads();
    for (int off = 1; off < CHUNK; off <<= 1) {
        int t = (tid >= off) ? sh[tid - off] : 0;
        __syncthreads();
        sh[tid] += t;
        __syncthreads();
    }
    if (i < NN) {
        int excl = sh[tid] - v + g_csums[blockIdx.x];
        g_rowptr[i] = excl;
        g_cur[i] = excl;
    }
}
__global__ __launch_bounds__(256) void k_fill() {
    int e = blockIdx.x * blockDim.x + threadIdx.x;
    if (e >= EE) return;
    int slot = atomicAdd(&g_cur[g_dst[e]], 1);
    g_csrc[slot] = g_src[e];
}

// ---------------- TF32 tensor-core GEMM (double-buffered, reg-prefetch) ----------
// block 128x128, 128 threads (4 warps 2x2), warp tile 64x64, BK=16.
#define BM 128
#define BN 128
#define BK 16

__device__ __forceinline__ uint32_t f2tf32(float x) {
    uint32_t r;
    asm("cvt.rna.tf32.f32 %0, %1;" : "=r"(r) : "f"(x));
    return r;
}

__device__ __forceinline__ void mma_tf32(float* d, const uint32_t* a, const uint32_t* b) {
    asm volatile(
        "mma.sync.aligned.m16n8k8.row.col.f32.tf32.tf32.f32 "
        "{%0,%1,%2,%3}, {%4,%5,%6,%7}, {%8,%9}, {%0,%1,%2,%3};"
        : "+f"(d[0]), "+f"(d[1]), "+f"(d[2]), "+f"(d[3])
        : "r"(a[0]), "r"(a[1]), "r"(a[2]), "r"(a[3]), "r"(b[0]), "r"(b[1]));
}

__device__ __forceinline__ void ld_tiles(
    const float* __restrict__ A, const float* __restrict__ B,
    int M, int K, int Nld, int m0, int n0, int kc, int tid,
    float4 ar[4], float4 br[4]) {
#pragma unroll
    for (int i = 0; i < 4; i++) {
        int f = tid + i * 128;
        int m = f >> 2, k4 = (f & 3) * 4;
        ar[i] = (m0 + m < M)
                    ? *(const float4*)(A + (size_t)(m0 + m) * K + kc + k4)
                    : make_float4(0.f, 0.f, 0.f, 0.f);
    }
#pragma unroll
    for (int i = 0; i < 4; i++) {
        int f = tid + i * 128;
        int k = f >> 5, n4 = (f & 31) * 4;
        br[i] = *(const float4*)(B + (size_t)(kc + k) * Nld + n0 + n4);
    }
}

__device__ __forceinline__ void st_tiles(
    float (*As)[BK + 4], float (*Bs)[BN + 8], int tid,
    const float4 ar[4], const float4 br[4]) {
#pragma unroll
    for (int i = 0; i < 4; i++) {
        int f = tid + i * 128;
        int m = f >> 2, k4 = (f & 3) * 4;
        float4 cv;
        cv.x = __uint_as_float(f2tf32(ar[i].x));
        cv.y = __uint_as_float(f2tf32(ar[i].y));
        cv.z = __uint_as_float(f2tf32(ar[i].z));
        cv.w = __uint_as_float(f2tf32(ar[i].w));
        *(float4*)&As[m][k4] = cv;
    }
#pragma unroll
    for (int i = 0; i < 4; i++) {
        int f = tid + i * 128;
        int k = f >> 5, n4 = (f & 31) * 4;
        float4 cv;
        cv.x = __uint_as_float(f2tf32(br[i].x));
        cv.y = __uint_as_float(f2tf32(br[i].y));
        cv.z = __uint_as_float(f2tf32(br[i].z));
        cv.w = __uint_as_float(f2tf32(br[i].w));
        *(float4*)&Bs[k][n4] = cv;
    }
}

template <int ACT>
__device__ __forceinline__ void gemm_core(
    const float* __restrict__ A, const float* __restrict__ B,
    const float* __restrict__ bias, float* __restrict__ C,
    int M, int K, int Nld, int m0, int n0,
    float As[2][BM][BK + 4], float Bs[2][BK][BN + 8]) {
    int tid = threadIdx.x;
    int warp = tid >> 5, lane = tid & 31;
    int wm = (warp >> 1) * 64, wn = (warp & 1) * 64;
    int g = lane >> 2, t = lane & 3;

    float acc[4][8][4];
#pragma unroll
    for (int a = 0; a < 4; a++)
#pragma unroll
        for (int b = 0; b < 8; b++)
#pragma unroll
            for (int c = 0; c < 4; c++) acc[a][b][c] = 0.f;

    float4 ar[4], br[4];
    ld_tiles(A, B, M, K, Nld, m0, n0, 0, tid, ar, br);
    st_tiles(As[0], Bs[0], tid, ar, br);
    __syncthreads();

    int nit = K / BK;
    for (int it = 0; it < nit; it++) {
        int cur = it & 1;
        if (it + 1 < nit)
            ld_tiles(A, B, M, K, Nld, m0, n0, (it + 1) * BK, tid, ar, br);

#pragma unroll
        for (int kk = 0; kk < BK; kk += 8) {
            uint32_t af[4][4];
#pragma unroll
            for (int tm = 0; tm < 4; tm++) {
                int mb = wm + tm * 16;
                af[tm][0] = __float_as_uint(As[cur][mb + g][kk + t]);
                af[tm][1] = __float_as_uint(As[cur][mb + g + 8][kk + t]);
                af[tm][2] = __float_as_uint(As[cur][mb + g][kk + t + 4]);
                af[tm][3] = __float_as_uint(As[cur][mb + g + 8][kk + t + 4]);
            }
            uint32_t bf[8][2];
#pragma unroll
            for (int tn = 0; tn < 8; tn++) {
                int nb = wn + tn * 8;
                bf[tn][0] = __float_as_uint(Bs[cur][kk + t][nb + g]);
                bf[tn][1] = __float_as_uint(Bs[cur][kk + t + 4][nb + g]);
            }
#pragma unroll
            for (int tm = 0; tm < 4; tm++)
#pragma unroll
                for (int tn = 0; tn < 8; tn++)
                    mma_tf32(acc[tm][tn], af[tm], bf[tn]);
        }

        if (it + 1 < nit)
            st_tiles(As[cur ^ 1], Bs[cur ^ 1], tid, ar, br);
        __syncthreads();
    }

    // epilogue: c0,c1 row g cols 2t,2t+1 ; c2,c3 row g+8
#pragma unroll
    for (int tm = 0; tm < 4; tm++) {
        int r0 = m0 + wm + tm * 16 + g;
        int r1 = r0 + 8;
#pragma unroll
        for (int tn = 0; tn < 8; tn++) {
            int cb = n0 + wn + tn * 8 + 2 * t;
            float b0 = __ldg(bias + cb);
            float b1 = __ldg(bias + cb + 1);
            float v00 = acc[tm][tn][0] + b0;
            float v01 = acc[tm][tn][1] + b1;
            float v10 = acc[tm][tn][2] + b0;
            float v11 = acc[tm][tn][3] + b1;
            if (ACT == 1) {
                v00 = fmaxf(v00, 0.f); v01 = fmaxf(v01, 0.f);
                v10 = fmaxf(v10, 0.f); v11 = fmaxf(v11, 0.f);
            }
            if (ACT == 2) {
                v00 = 0.5f * v00 * (1.f + erff(v00 * 0.70710678118654752f));
                v01 = 0.5f * v01 * (1.f + erff(v01 * 0.70710678118654752f));
                v10 = 0.5f * v10 * (1.f + erff(v10 * 0.70710678118654752f));
                v11 = 0.5f * v11 * (1.f + erff(v11 * 0.70710678118654752f));
            }
            if (r0 < M) *(float2*)(C + (size_t)r0 * Nld + cb) = make_float2(v00, v01);
            if (r1 < M) *(float2*)(C + (size_t)r1 * Nld + cb) = make_float2(v10, v11);
        }
    }
}

template <int ACT>
__global__ __launch_bounds__(128) void gemm_tf32(
    const float* __restrict__ A, const float* __restrict__ B,
    const float* __restrict__ bias, float* __restrict__ C,
    int M, int K, int Nld) {
    __shared__ __align__(16) float As[2][BM][BK + 4];
    __shared__ __align__(16) float Bs[2][BK][BN + 8];
    gemm_core<ACT>(A, B, bias, C, M, K, Nld, blockIdx.x * BM, blockIdx.y * BN,
                   As, Bs);
}

// fused Q/K/V/SK projection: grid.y in [0,4) selects operator
__global__ __launch_bounds__(128) void gemm_qkvsk(
    const float* __restrict__ A,
    const float* __restrict__ Wq, const float* __restrict__ Wk,
    const float* __restrict__ Wv, const float* __restrict__ Wsk,
    const float* __restrict__ bq, const float* __restrict__ bk,
    const float* __restrict__ bv, const float* __restrict__ bsk, int l) {
    __shared__ __align__(16) float As[2][BM][BK + 4];
    __shared__ __align__(16) float Bs[2][BK][BN + 8];
    const float* B;
    const float* bias;
    float* C;
    switch (blockIdx.y) {
        case 0: B = Wq;  bias = bq;  C = g_q;  break;
        case 1: B = Wk;  bias = bk;  C = g_k;  break;
        case 2: B = Wv;  bias = bv;  C = g_v;  break;
        default: B = Wsk; bias = bsk; C = g_sk; break;
    }
    B += (size_t)l * HIDC * HIDC;
    bias += l * HIDC;
    gemm_core<0>(A, B, bias, C, NN, HIDC, HIDC, blockIdx.x * BM, 0, As, Bs);
}

// ---------------- fused attention: warp per dst node, online softmax, prefetch --
__global__ __launch_bounds__(256) void attn_fused() {
    int node = (blockIdx.x * blockDim.x + threadIdx.x) >> 5;
    if (node >= NN) return;
    int lane = threadIdx.x & 31;
    int beg = g_rowptr[node], end = g_rowptr[node + 1];
    size_t qb = (size_t)node * HIDC + lane * 4;
    float4 qv = *(const float4*)(g_q + qb);
    float m = -INFINITY, l = 0.f;
    float4 acc = make_float4(0.f, 0.f, 0.f, 0.f);
    if (beg < end) {
        int s = g_csrc[beg];
        size_t sb = (size_t)s * HIDC + lane * 4;
        float4 kv = *(const float4*)(g_k + sb);
        float4 vv = *(const float4*)(g_v + sb);
        for (int e = beg; e < end; e++) {
            float4 kc = kv, vc = vv;
            if (e + 1 < end) {
                int sn = g_csrc[e + 1];
                size_t sb2 = (size_t)sn * HIDC + lane * 4;
                kv = *(const float4*)(g_k + sb2);
                vv = *(const float4*)(g_v + sb2);
            }
            float p = qv.x * kc.x + qv.y * kc.y + qv.z * kc.z + qv.w * kc.w;
            p += __shfl_xor_sync(0xffffffffu, p, 8, 16);
            p += __shfl_xor_sync(0xffffffffu, p, 4, 16);
            p += __shfl_xor_sync(0xffffffffu, p, 2, 16);
            p += __shfl_xor_sync(0xffffffffu, p, 1, 16);
            float sc = p * 0.125f;  // 1/sqrt(64)
            float mn = fmaxf(m, sc);
            float scale = __expf(m - mn);
            float w = __expf(sc - mn);
            l = l * scale + w;
            acc.x = acc.x * scale + w * vc.x;
            acc.y = acc.y * scale + w * vc.y;
            acc.z = acc.z * scale + w * vc.z;
            acc.w = acc.w * scale + w * vc.w;
            m = mn;
        }
    }
    float inv = (l > 0.f) ? 1.f / l : 0.f;
    acc.x *= inv; acc.y *= inv; acc.z *= inv; acc.w *= inv;
    *(float4*)(g_attn + qb) = acc;
}

// ---------------- layernorm kernels (warp per row, 128 cols) ----------------
__global__ __launch_bounds__(256) void ln3_kernel(
    const float* __restrict__ g, const float* __restrict__ bt) {
    int row = (blockIdx.x * blockDim.x + threadIdx.x) >> 5;
    if (row >= NN) return;
    int lane = threadIdx.x & 31;
    size_t base = (size_t)row * HIDC + lane * 4;
    float4 a = *(const float4*)(g_z + base);
    float4 b = *(const float4*)(g_attn + base);
    float4 c = *(const float4*)(g_sk + base);
    float v0 = a.x + b.x + c.x, v1 = a.y + b.y + c.y;
    float v2 = a.z + b.z + c.z, v3 = a.w + b.w + c.w;
    float s = v0 + v1 + v2 + v3;
#pragma unroll
    for (int o = 16; o > 0; o >>= 1) s += __shfl_xor_sync(0xffffffffu, s, o);
    float mu = s * (1.f / HIDC);
    float d0 = v0 - mu, d1 = v1 - mu, d2 = v2 - mu, d3 = v3 - mu;
    float ss = d0 * d0 + d1 * d1 + d2 * d2 + d3 * d3;
#pragma unroll
    for (int o = 16; o > 0; o >>= 1) ss += __shfl_xor_sync(0xffffffffu, ss, o);
    float rs = rsqrtf(ss * (1.f / HIDC) + EPSLN);
    int col = lane * 4;
    float4 o4;
    o4.x = d0 * rs * g[col + 0] + bt[col + 0];
    o4.y = d1 * rs * g[col + 1] + bt[col + 1];
    o4.z = d2 * rs * g[col + 2] + bt[col + 2];
    o4.w = d3 * rs * g[col + 3] + bt[col + 3];
    *(float4*)(g_h + base) = o4;
}

// z = relu(LN(h+u)); out += betas[li]*z
__global__ __launch_bounds__(256) void lnacc_kernel(
    const float* __restrict__ g, const float* __restrict__ bt,
    float* __restrict__ out, int li) {
    int row = (blockIdx.x * blockDim.x + threadIdx.x) >> 5;
    if (row >= NN) return;
    int lane = threadIdx.x & 31;
    size_t base = (size_t)row * HIDC + lane * 4;
    float4 a = *(const float4*)(g_h + base);
    float4 b = *(const float4*)(g_u + base);
    float v0 = a.x + b.x, v1 = a.y + b.y, v2 = a.z + b.z, v3 = a.w + b.w;
    float s = v0 + v1 + v2 + v3;
#pragma unroll
    for (int o = 16; o > 0; o >>= 1) s += __shfl_xor_sync(0xffffffffu, s, o);
    float mu = s * (1.f / HIDC);
    float d0 = v0 - mu, d1 = v1 - mu, d2 = v2 - mu, d3 = v3 - mu;
    float ss = d0 * d0 + d1 * d1 + d2 * d2 + d3 * d3;
#pragma unroll
    for (int o = 16; o > 0; o >>= 1) ss += __shfl_xor_sync(0xffffffffu, ss, o);
    float rs = rsqrtf(ss * (1.f / HIDC) + EPSLN);
    int col = lane * 4;
    float z0 = fmaxf(d0 * rs * g[col + 0] + bt[col + 0], 0.f);
    float z1 = fmaxf(d1 * rs * g[col + 1] + bt[col + 1], 0.f);
    float z2 = fmaxf(d2 * rs * g[col + 2] + bt[col + 2], 0.f);
    float z3 = fmaxf(d3 * rs * g[col + 3] + bt[col + 3], 0.f);
    float bb = g_betas[li];
    *(float4*)(g_z + base) = make_float4(z0, z1, z2, z3);
    float4 oo = *(float4*)(out + base);
    oo.x += bb * z0; oo.y += bb * z1; oo.z += bb * z2; oo.w += bb * z3;
    *(float4*)(out + base) = oo;
}

__global__ __launch_bounds__(256) void init_acc(float* __restrict__ out) {
    int i = blockIdx.x * blockDim.x + threadIdx.x;
    if (i < NN * HIDC) out[i] = g_betas[0] * g_z[i];
}

// ---------------- host launcher ----------------
extern "C" void kernel_launch(void* const* d_in, const int* in_sizes, int n_in,
                              void* d_out, int out_size) {
    const float* x    = (const float*)d_in[0];
    const void*  ei   = d_in[1];
    const float* Win  = (const float*)d_in[2];
    const float* b_in = (const float*)d_in[3];
    const float* Wq   = (const float*)d_in[4];
    const float* bq   = (const float*)d_in[5];
    const float* Wk   = (const float*)d_in[6];
    const float* bk   = (const float*)d_in[7];
    const float* Wv   = (const float*)d_in[8];
    const float* bv   = (const float*)d_in[9];
    const float* Wsk  = (const float*)d_in[10];
    const float* bsk  = (const float*)d_in[11];
    const float* W1   = (const float*)d_in[12];
    const float* b1   = (const float*)d_in[13];
    const float* W2   = (const float*)d_in[14];
    const float* b2   = (const float*)d_in[15];
    const float* g1   = (const float*)d_in[16];
    const float* bt1  = (const float*)d_in[17];
    const float* g2   = (const float*)d_in[18];
    const float* bt2  = (const float*)d_in[19];
    const float* beta = (const float*)d_in[20];
    float* out = (float*)d_out;

    float *z, *h, *t, *u;
    cudaGetSymbolAddress((void**)&z, g_z);
    cudaGetSymbolAddress((void**)&h, g_h);
    cudaGetSymbolAddress((void**)&t, g_t);
    cudaGetSymbolAddress((void**)&u, g_u);

    const int GM = (NN + BM - 1) / BM;  // 391

    // launch order chosen so ncu (-s 5 -c 1) captures the fused QKVSK GEMM
    sniff_kernel<<<1, 32>>>((const unsigned*)ei);                       // 0
    convert_edges<<<(EE + 255) / 256, 256>>>(ei);                       // 1
    beta_softmax<<<1, 32>>>(beta);                                      // 2
    gemm_tf32<1><<<dim3(GM, 1), 128>>>(x, Win, b_in, z, NN, HIDC, HIDC);// 3
    init_acc<<<(NN * HIDC + 255) / 256, 256>>>(out);                    // 4
    gemm_qkvsk<<<dim3(GM, 4), 128>>>(z, Wq, Wk, Wv, Wsk,                // 5 (captured)
                                     bq, bk, bv, bsk, 0);

    // CSR build (once; needed before first attn)
    k_clear_deg<<<(NN + 255) / 256, 256>>>();
    k_hist<<<(EE + 255) / 256, 256>>>();
    k_chunksum<<<NCHK, CHUNK>>>();
    k_scanchunks<<<1, 32>>>();
    k_rowptr<<<NCHK, CHUNK>>>();
    k_fill<<<(EE + 255) / 256, 256>>>();

    for (int l = 0; l < NLAYERS; l++) {
        if (l > 0)
            gemm_qkvsk<<<dim3(GM, 4), 128>>>(z, Wq, Wk, Wv, Wsk,
                                             bq, bk, bv, bsk, l);

        attn_fused<<<(NN * 32 + 255) / 256, 256>>>();

        ln3_kernel<<<(NN + 7) / 8, 256>>>(g1 + l * HIDC, bt1 + l * HIDC);

        gemm_tf32<2><<<dim3(GM, 2), 128>>>(h, W1 + (size_t)l * HIDC * FFC,
                                           b1 + l * FFC, t, NN, HIDC, FFC);
        gemm_tf32<0><<<dim3(GM, 1), 128>>>(t, W2 + (size_t)l * FFC * HIDC,
                                           b2 + l * HIDC, u, NN, FFC, HIDC);

        lnacc_kernel<<<(NN + 7) / 8, 256>>>(g2 + l * HIDC, bt2 + l * HIDC, out, l + 1);
    }
}

// round 6
// speedup vs baseline: 2.9131x; 1.0317x over previous
#include <cuda_runtime.h>
#include <math.h>
#include <stdint.h>

#define NN 50000
#define EE 800000
#define HIDC 128
#define FFC 256
#define NLAYERS 6
#define EPSLN 1e-5f

// ---------------- scratch (device globals; no allocation allowed) ----------------
__device__ float g_z[NN * HIDC];
__device__ float g_q[NN * HIDC];
__device__ float g_k[NN * HIDC];
__device__ float g_v[NN * HIDC];
__device__ float g_sk[NN * HIDC];
__device__ float g_attn[NN * HIDC];
__device__ float g_h[NN * HIDC];
__device__ float g_t[NN * FFC];
__device__ float g_u[NN * HIDC];
__device__ int g_src[EE];
__device__ int g_dst[EE];
__device__ int g_deg[NN];
__device__ int g_rowptr[NN + 1];
__device__ int g_cur[NN];
__device__ int g_csrc[EE];
__device__ int g_csums[128];
__device__ float g_betas[NLAYERS + 2];
__device__ int g_flag[1];

// tf32-preconverted weights
#define OFF_WQ  16384
#define OFF_WK  (OFF_WQ + NLAYERS * HIDC * HIDC)
#define OFF_WV  (OFF_WK + NLAYERS * HIDC * HIDC)
#define OFF_WSK (OFF_WV + NLAYERS * HIDC * HIDC)
#define OFF_W1  (OFF_WSK + NLAYERS * HIDC * HIDC)
#define OFF_W2  (OFF_W1 + NLAYERS * HIDC * FFC)
#define TOTW    (OFF_W2 + NLAYERS * FFC * HIDC)
__device__ float g_wt[TOTW];

#define CHUNK 512
#define NCHK ((NN + CHUNK - 1) / CHUNK)   // 98

// ---------------- helpers ----------------
__device__ __forceinline__ uint32_t f2tf32(float x) {
    uint32_t r;
    asm("cvt.rna.tf32.f32 %0, %1;" : "=r"(r) : "f"(x));
    return r;
}

__device__ __forceinline__ void mma_tf32(float* d, const uint32_t* a, const uint32_t* b) {
    asm volatile(
        "mma.sync.aligned.m16n8k8.row.col.f32.tf32.tf32.f32 "
        "{%0,%1,%2,%3}, {%4,%5,%6,%7}, {%8,%9}, {%0,%1,%2,%3};"
        : "+f"(d[0]), "+f"(d[1]), "+f"(d[2]), "+f"(d[3])
        : "r"(a[0]), "r"(a[1]), "r"(a[2]), "r"(a[3]), "r"(b[0]), "r"(b[1]));
}

__device__ __forceinline__ void cp16(uint32_t saddr, const void* g) {
    asm volatile("cp.async.ca.shared.global [%0], [%1], 16;" ::"r"(saddr), "l"(g));
}
__device__ __forceinline__ void cp_commit() {
    asm volatile("cp.async.commit_group;");
}
__device__ __forceinline__ void cp_wait0() {
    asm volatile("cp.async.wait_group 0;");
}

// ---------------- edge index dtype sniff + convert ----------------
__global__ void sniff_kernel(const unsigned* __restrict__ w) {
    if (threadIdx.x == 0 && blockIdx.x == 0) {
        int is64 = 1;
        for (int i = 1; i < 64; i += 2)
            if (w[i] != 0u) { is64 = 0; break; }
        g_flag[0] = is64;
    }
}

__global__ __launch_bounds__(256) void convert_edges(const void* __restrict__ ei) {
    int e = blockIdx.x * blockDim.x + threadIdx.x;
    if (e >= EE) return;
    if (g_flag[0]) {
        const long long* p = (const long long*)ei;
        g_src[e] = (int)p[e];
        g_dst[e] = (int)p[EE + e];
    } else {
        const int* p = (const int*)ei;
        g_src[e] = p[e];
        g_dst[e] = p[EE + e];
    }
}

__global__ void beta_softmax(const float* __restrict__ beta) {
    if (threadIdx.x == 0 && blockIdx.x == 0) {
        float m = -1e30f;
        for (int i = 0; i < NLAYERS + 1; i++) m = fmaxf(m, beta[i]);
        float s = 0.f;
        for (int i = 0; i < NLAYERS + 1; i++) {
            float e = expf(beta[i] - m);
            g_betas[i] = e;
            s += e;
        }
        for (int i = 0; i < NLAYERS + 1; i++) g_betas[i] /= s;
    }
}

// ---------------- one-shot weight tf32 preconversion ----------------
__global__ __launch_bounds__(256) void convW(
    const float* __restrict__ Win, const float* __restrict__ Wq,
    const float* __restrict__ Wk, const float* __restrict__ Wv,
    const float* __restrict__ Wsk, const float* __restrict__ W1,
    const float* __restrict__ W2) {
    int i = blockIdx.x * blockDim.x + threadIdx.x;
    if (i >= TOTW) return;
    const float* src;
    int off;
    if (i < OFF_WQ)       { src = Win; off = i; }
    else if (i < OFF_WK)  { src = Wq;  off = i - OFF_WQ; }
    else if (i < OFF_WV)  { src = Wk;  off = i - OFF_WK; }
    else if (i < OFF_WSK) { src = Wv;  off = i - OFF_WV; }
    else if (i < OFF_W1)  { src = Wsk; off = i - OFF_WSK; }
    else if (i < OFF_W2)  { src = W1;  off = i - OFF_W1; }
    else                  { src = W2;  off = i - OFF_W2; }
    g_wt[i] = __uint_as_float(f2tf32(src[off]));
}

// ---------------- CSR build ----------------
__global__ __launch_bounds__(256) void k_clear_deg() {
    int i = blockIdx.x * blockDim.x + threadIdx.x;
    if (i < NN) g_deg[i] = 0;
}
__global__ __launch_bounds__(256) void k_hist() {
    int e = blockIdx.x * blockDim.x + threadIdx.x;
    if (e < EE) atomicAdd(&g_deg[g_dst[e]], 1);
}
__global__ __launch_bounds__(CHUNK) void k_chunksum() {
    __shared__ int sh[CHUNK];
    int tid = threadIdx.x;
    int i = blockIdx.x * CHUNK + tid;
    sh[tid] = (i < NN) ? g_deg[i] : 0;
    __syncthreads();
    for (int off = CHUNK / 2; off > 0; off >>= 1) {
        if (tid < off) sh[tid] += sh[tid + off];
        __syncthreads();
    }
    if (tid == 0) g_csums[blockIdx.x] = sh[0];
}
__global__ void k_scanchunks() {
    if (threadIdx.x == 0 && blockIdx.x == 0) {
        int run = 0;
        for (int c = 0; c < NCHK; c++) {
            int v = g_csums[c];
            g_csums[c] = run;
            run += v;
        }
        g_rowptr[NN] = run;
    }
}
__global__ __launch_bounds__(CHUNK) void k_rowptr() {
    __shared__ int sh[CHUNK];
    int tid = threadIdx.x;
    int i = blockIdx.x * CHUNK + tid;
    int v = (i < NN) ? g_deg[i] : 0;
    sh[tid] = v;
    __syncthreads();
    for (int off = 1; off < CHUNK; off <<= 1) {
        int t = (tid >= off) ? sh[tid - off] : 0;
        __syncthreads();
        sh[tid] += t;
        __syncthreads();
    }
    if (i < NN) {
        int excl = sh[tid] - v + g_csums[blockIdx.x];
        g_rowptr[i] = excl;
        g_cur[i] = excl;
    }
}
__global__ __launch_bounds__(256) void k_fill() {
    int e = blockIdx.x * blockDim.x + threadIdx.x;
    if (e >= EE) return;
    int slot = atomicAdd(&g_cur[g_dst[e]], 1);
    g_csrc[slot] = g_src[e];
}

// ---------------- TF32 GEMM: 256 thr, 8 warps (2x4), warp tile 64x32 ----------
// B operand is pre-converted tf32 (g_wt) and staged via cp.async.
#define BM 128
#define BN 128
#define BK 16

__device__ __forceinline__ void ldA(
    const float* __restrict__ A, int M, int K, int m0, int kc, int tid,
    float4 ar[2]) {
#pragma unroll
    for (int i = 0; i < 2; i++) {
        int f = tid + i * 256;
        int m = f >> 2, k4 = (f & 3) * 4;
        ar[i] = (m0 + m < M)
                    ? *(const float4*)(A + (size_t)(m0 + m) * K + kc + k4)
                    : make_float4(0.f, 0.f, 0.f, 0.f);
    }
}

__device__ __forceinline__ void stA(float (*As)[BK + 4], int tid,
                                    const float4 ar[2]) {
#pragma unroll
    for (int i = 0; i < 2; i++) {
        int f = tid + i * 256;
        int m = f >> 2, k4 = (f & 3) * 4;
        float4 cv;
        cv.x = __uint_as_float(f2tf32(ar[i].x));
        cv.y = __uint_as_float(f2tf32(ar[i].y));
        cv.z = __uint_as_float(f2tf32(ar[i].z));
        cv.w = __uint_as_float(f2tf32(ar[i].w));
        *(float4*)&As[m][k4] = cv;
    }
}

__device__ __forceinline__ void cpB(float (*Bs)[BN + 8],
                                    const float* __restrict__ B, int Nld,
                                    int n0, int kc, int tid) {
#pragma unroll
    for (int i = 0; i < 2; i++) {
        int f = tid + i * 256;
        int k = f >> 5, n4 = (f & 31) * 4;
        uint32_t sa = (uint32_t)__cvta_generic_to_shared(&Bs[k][n4]);
        cp16(sa, B + (size_t)(kc + k) * Nld + n0 + n4);
    }
}

template <int ACT>
__device__ __forceinline__ void gemm_core(
    const float* __restrict__ A, const float* __restrict__ B,
    const float* __restrict__ bias, float* __restrict__ C,
    int M, int K, int Nld, int m0, int n0,
    float As[2][BM][BK + 4], float Bs[2][BK][BN + 8]) {
    int tid = threadIdx.x;
    int warp = tid >> 5, lane = tid & 31;
    int wm = (warp >> 2) * 64, wn = (warp & 3) * 32;
    int g = lane >> 2, t = lane & 3;

    float acc[4][4][4];
#pragma unroll
    for (int a = 0; a < 4; a++)
#pragma unroll
        for (int b = 0; b < 4; b++)
#pragma unroll
            for (int c = 0; c < 4; c++) acc[a][b][c] = 0.f;

    float4 ar[2];
    ldA(A, M, K, m0, 0, tid, ar);
    cpB(Bs[0], B, Nld, n0, 0, tid);
    stA(As[0], tid, ar);
    cp_commit();
    cp_wait0();
    __syncthreads();

    int nit = K / BK;
    for (int it = 0; it < nit; it++) {
        int cur = it & 1;
        if (it + 1 < nit) {
            ldA(A, M, K, m0, (it + 1) * BK, tid, ar);
            cpB(Bs[cur ^ 1], B, Nld, n0, (it + 1) * BK, tid);
            cp_commit();
        }

#pragma unroll
        for (int kk = 0; kk < BK; kk += 8) {
            uint32_t af[4][4];
#pragma unroll
            for (int tm = 0; tm < 4; tm++) {
                int mb = wm + tm * 16;
                af[tm][0] = __float_as_uint(As[cur][mb + g][kk + t]);
                af[tm][1] = __float_as_uint(As[cur][mb + g + 8][kk + t]);
                af[tm][2] = __float_as_uint(As[cur][mb + g][kk + t + 4]);
                af[tm][3] = __float_as_uint(As[cur][mb + g + 8][kk + t + 4]);
            }
            uint32_t bf[4][2];
#pragma unroll
            for (int tn = 0; tn < 4; tn++) {
                int nb = wn + tn * 8;
                bf[tn][0] = __float_as_uint(Bs[cur][kk + t][nb + g]);
                bf[tn][1] = __float_as_uint(Bs[cur][kk + t + 4][nb + g]);
            }
#pragma unroll
            for (int tm = 0; tm < 4; tm++)
#pragma unroll
                for (int tn = 0; tn < 4; tn++)
                    mma_tf32(acc[tm][tn], af[tm], bf[tn]);
        }

        if (it + 1 < nit) stA(As[cur ^ 1], tid, ar);
        cp_wait0();
        __syncthreads();
    }

    // epilogue: c0,c1 row g cols 2t,2t+1 ; c2,c3 row g+8
#pragma unroll
    for (int tm = 0; tm < 4; tm++) {
        int r0 = m0 + wm + tm * 16 + g;
        int r1 = r0 + 8;
#pragma unroll
        for (int tn = 0; tn < 4; tn++) {
            int cb = n0 + wn + tn * 8 + 2 * t;
            float b0 = __ldg(bias + cb);
            float b1 = __ldg(bias + cb + 1);
            float v00 = acc[tm][tn][0] + b0;
            float v01 = acc[tm][tn][1] + b1;
            float v10 = acc[tm][tn][2] + b0;
            float v11 = acc[tm][tn][3] + b1;
            if (ACT == 1) {
                v00 = fmaxf(v00, 0.f); v01 = fmaxf(v01, 0.f);
                v10 = fmaxf(v10, 0.f); v11 = fmaxf(v11, 0.f);
            }
            if (ACT == 2) {
                v00 = 0.5f * v00 * (1.f + erff(v00 * 0.70710678118654752f));
                v01 = 0.5f * v01 * (1.f + erff(v01 * 0.70710678118654752f));
                v10 = 0.5f * v10 * (1.f + erff(v10 * 0.70710678118654752f));
                v11 = 0.5f * v11 * (1.f + erff(v11 * 0.70710678118654752f));
            }
            if (r0 < M) *(float2*)(C + (size_t)r0 * Nld + cb) = make_float2(v00, v01);
            if (r1 < M) *(float2*)(C + (size_t)r1 * Nld + cb) = make_float2(v10, v11);
        }
    }
}

template <int ACT>
__global__ __launch_bounds__(256) void gemm_tf32(
    const float* __restrict__ A, const float* __restrict__ B,
    const float* __restrict__ bias, float* __restrict__ C,
    int M, int K, int Nld) {
    __shared__ __align__(16) float As[2][BM][BK + 4];
    __shared__ __align__(16) float Bs[2][BK][BN + 8];
    gemm_core<ACT>(A, B, bias, C, M, K, Nld, blockIdx.x * BM, blockIdx.y * BN,
                   As, Bs);
}

// fused Q/K/V/SK projection: grid.y in [0,4) selects operator
__global__ __launch_bounds__(256) void gemm_qkvsk(
    const float* __restrict__ A, const float* __restrict__ wt,
    const float* __restrict__ bq, const float* __restrict__ bk,
    const float* __restrict__ bv, const float* __restrict__ bsk, int l) {
    __shared__ __align__(16) float As[2][BM][BK + 4];
    __shared__ __align__(16) float Bs[2][BK][BN + 8];
    const float* B;
    const float* bias;
    float* C;
    switch (blockIdx.y) {
        case 0: B = wt + OFF_WQ;  bias = bq;  C = g_q;  break;
        case 1: B = wt + OFF_WK;  bias = bk;  C = g_k;  break;
        case 2: B = wt + OFF_WV;  bias = bv;  C = g_v;  break;
        default: B = wt + OFF_WSK; bias = bsk; C = g_sk; break;
    }
    B += (size_t)l * HIDC * HIDC;
    bias += l * HIDC;
    gemm_core<0>(A, B, bias, C, NN, HIDC, HIDC, blockIdx.x * BM, 0, As, Bs);
}

// ---------------- fused attention: warp per dst node, online softmax, prefetch --
__global__ __launch_bounds__(256) void attn_fused() {
    int node = (blockIdx.x * blockDim.x + threadIdx.x) >> 5;
    if (node >= NN) return;
    int lane = threadIdx.x & 31;
    int beg = g_rowptr[node], end = g_rowptr[node + 1];
    size_t qb = (size_t)node * HIDC + lane * 4;
    float4 qv = *(const float4*)(g_q + qb);
    float m = -INFINITY, l = 0.f;
    float4 acc = make_float4(0.f, 0.f, 0.f, 0.f);
    if (beg < end) {
        int s = g_csrc[beg];
        size_t sb = (size_t)s * HIDC + lane * 4;
        float4 kv = *(const float4*)(g_k + sb);
        float4 vv = *(const float4*)(g_v + sb);
        for (int e = beg; e < end; e++) {
            float4 kc = kv, vc = vv;
            if (e + 1 < end) {
                int sn = g_csrc[e + 1];
                size_t sb2 = (size_t)sn * HIDC + lane * 4;
                kv = *(const float4*)(g_k + sb2);
                vv = *(const float4*)(g_v + sb2);
            }
            float p = qv.x * kc.x + qv.y * kc.y + qv.z * kc.z + qv.w * kc.w;
            p += __shfl_xor_sync(0xffffffffu, p, 8, 16);
            p += __shfl_xor_sync(0xffffffffu, p, 4, 16);
            p += __shfl_xor_sync(0xffffffffu, p, 2, 16);
            p += __shfl_xor_sync(0xffffffffu, p, 1, 16);
            float sc = p * 0.125f;  // 1/sqrt(64)
            float mn = fmaxf(m, sc);
            float scale = __expf(m - mn);
            float w = __expf(sc - mn);
            l = l * scale + w;
            acc.x = acc.x * scale + w * vc.x;
            acc.y = acc.y * scale + w * vc.y;
            acc.z = acc.z * scale + w * vc.z;
            acc.w = acc.w * scale + w * vc.w;
            m = mn;
        }
    }
    float inv = (l > 0.f) ? 1.f / l : 0.f;
    acc.x *= inv; acc.y *= inv; acc.z *= inv; acc.w *= inv;
    *(float4*)(g_attn + qb) = acc;
}

// ---------------- layernorm kernels (warp per row, 128 cols) ----------------
__global__ __launch_bounds__(256) void ln3_kernel(
    const float* __restrict__ g, const float* __restrict__ bt) {
    int row = (blockIdx.x * blockDim.x + threadIdx.x) >> 5;
    if (row >= NN) return;
    int lane = threadIdx.x & 31;
    size_t base = (size_t)row * HIDC + lane * 4;
    float4 a = *(const float4*)(g_z + base);
    float4 b = *(const float4*)(g_attn + base);
    float4 c = *(const float4*)(g_sk + base);
    float v0 = a.x + b.x + c.x, v1 = a.y + b.y + c.y;
    float v2 = a.z + b.z + c.z, v3 = a.w + b.w + c.w;
    float s = v0 + v1 + v2 + v3;
#pragma unroll
    for (int o = 16; o > 0; o >>= 1) s += __shfl_xor_sync(0xffffffffu, s, o);
    float mu = s * (1.f / HIDC);
    float d0 = v0 - mu, d1 = v1 - mu, d2 = v2 - mu, d3 = v3 - mu;
    float ss = d0 * d0 + d1 * d1 + d2 * d2 + d3 * d3;
#pragma unroll
    for (int o = 16; o > 0; o >>= 1) ss += __shfl_xor_sync(0xffffffffu, ss, o);
    float rs = rsqrtf(ss * (1.f / HIDC) + EPSLN);
    int col = lane * 4;
    float4 o4;
    o4.x = d0 * rs * g[col + 0] + bt[col + 0];
    o4.y = d1 * rs * g[col + 1] + bt[col + 1];
    o4.z = d2 * rs * g[col + 2] + bt[col + 2];
    o4.w = d3 * rs * g[col + 3] + bt[col + 3];
    *(float4*)(g_h + base) = o4;
}

// z = relu(LN(h+u)); out += betas[li]*z
__global__ __launch_bounds__(256) void lnacc_kernel(
    const float* __restrict__ g, const float* __restrict__ bt,
    float* __restrict__ out, int li) {
    int row = (blockIdx.x * blockDim.x + threadIdx.x) >> 5;
    if (row >= NN) return;
    int lane = threadIdx.x & 31;
    size_t base = (size_t)row * HIDC + lane * 4;
    float4 a = *(const float4*)(g_h + base);
    float4 b = *(const float4*)(g_u + base);
    float v0 = a.x + b.x, v1 = a.y + b.y, v2 = a.z + b.z, v3 = a.w + b.w;
    float s = v0 + v1 + v2 + v3;
#pragma unroll
    for (int o = 16; o > 0; o >>= 1) s += __shfl_xor_sync(0xffffffffu, s, o);
    float mu = s * (1.f / HIDC);
    float d0 = v0 - mu, d1 = v1 - mu, d2 = v2 - mu, d3 = v3 - mu;
    float ss = d0 * d0 + d1 * d1 + d2 * d2 + d3 * d3;
#pragma unroll
    for (int o = 16; o > 0; o >>= 1) ss += __shfl_xor_sync(0xffffffffu, ss, o);
    float rs = rsqrtf(ss * (1.f / HIDC) + EPSLN);
    int col = lane * 4;
    float z0 = fmaxf(d0 * rs * g[col + 0] + bt[col + 0], 0.f);
    float z1 = fmaxf(d1 * rs * g[col + 1] + bt[col + 1], 0.f);
    float z2 = fmaxf(d2 * rs * g[col + 2] + bt[col + 2], 0.f);
    float z3 = fmaxf(d3 * rs * g[col + 3] + bt[col + 3], 0.f);
    float bb = g_betas[li];
    *(float4*)(g_z + base) = make_float4(z0, z1, z2, z3);
    float4 oo = *(float4*)(out + base);
    oo.x += bb * z0; oo.y += bb * z1; oo.z += bb * z2; oo.w += bb * z3;
    *(float4*)(out + base) = oo;
}

__global__ __launch_bounds__(256) void init_acc(float* __restrict__ out) {
    int i = blockIdx.x * blockDim.x + threadIdx.x;
    if (i < NN * HIDC) out[i] = g_betas[0] * g_z[i];
}

// ---------------- host launcher ----------------
extern "C" void kernel_launch(void* const* d_in, const int* in_sizes, int n_in,
                              void* d_out, int out_size) {
    const float* x    = (const float*)d_in[0];
    const void*  ei   = d_in[1];
    const float* Win  = (const float*)d_in[2];
    const float* b_in = (const float*)d_in[3];
    const float* Wq   = (const float*)d_in[4];
    const float* bq   = (const float*)d_in[5];
    const float* Wk   = (const float*)d_in[6];
    const float* bk   = (const float*)d_in[7];
    const float* Wv   = (const float*)d_in[8];
    const float* bv   = (const float*)d_in[9];
    const float* Wsk  = (const float*)d_in[10];
    const float* bsk  = (const float*)d_in[11];
    const float* W1   = (const float*)d_in[12];
    const float* b1   = (const float*)d_in[13];
    const float* W2   = (const float*)d_in[14];
    const float* b2   = (const float*)d_in[15];
    const float* g1   = (const float*)d_in[16];
    const float* bt1  = (const float*)d_in[17];
    const float* g2   = (const float*)d_in[18];
    const float* bt2  = (const float*)d_in[19];
    const float* beta = (const float*)d_in[20];
    float* out = (float*)d_out;

    float *z, *h, *t, *u, *wt;
    cudaGetSymbolAddress((void**)&z, g_z);
    cudaGetSymbolAddress((void**)&h, g_h);
    cudaGetSymbolAddress((void**)&t, g_t);
    cudaGetSymbolAddress((void**)&u, g_u);
    cudaGetSymbolAddress((void**)&wt, g_wt);

    const int GM = (NN + BM - 1) / BM;  // 391

    // order chosen so ncu (-s 5 -c 1) captures the fused QKVSK GEMM at idx 5
    sniff_kernel<<<1, 32>>>((const unsigned*)ei);                        // 0
    convert_edges<<<(EE + 255) / 256, 256>>>(ei);                        // 1
    beta_softmax<<<1, 32>>>(beta);                                       // 2
    convW<<<(TOTW + 255) / 256, 256>>>(Win, Wq, Wk, Wv, Wsk, W1, W2);    // 3
    gemm_tf32<1><<<dim3(GM, 1), 256>>>(x, wt, b_in, z, NN, HIDC, HIDC);  // 4
    gemm_qkvsk<<<dim3(GM, 4), 256>>>(z, wt, bq, bk, bv, bsk, 0);         // 5

    init_acc<<<(NN * HIDC + 255) / 256, 256>>>(out);

    // CSR build (once; needed before first attn)
    k_clear_deg<<<(NN + 255) / 256, 256>>>();
    k_hist<<<(EE + 255) / 256, 256>>>();
    k_chunksum<<<NCHK, CHUNK>>>();
    k_scanchunks<<<1, 32>>>();
    k_rowptr<<<NCHK, CHUNK>>>();
    k_fill<<<(EE + 255) / 256, 256>>>();

    for (int l = 0; l < NLAYERS; l++) {
        if (l > 0)
            gemm_qkvsk<<<dim3(GM, 4), 256>>>(z, wt, bq, bk, bv, bsk, l);

        attn_fused<<<(NN * 32 + 255) / 256, 256>>>();

        ln3_kernel<<<(NN + 7) / 8, 256>>>(g1 + l * HIDC, bt1 + l * HIDC);

        gemm_tf32<2><<<dim3(GM, 2), 256>>>(h, wt + OFF_W1 + (size_t)l * HIDC * FFC,
                                           b1 + l * FFC, t, NN, HIDC, FFC);
        gemm_tf32<0><<<dim3(GM, 1), 256>>>(t, wt + OFF_W2 + (size_t)l * FFC * HIDC,
                                           b2 + l * HIDC, u, NN, FFC, HIDC);

        lnacc_kernel<<<(NN + 7) / 8, 256>>>(g2 + l * HIDC, bt2 + l * HIDC, out, l + 1);
    }
}

// round 7
// speedup vs baseline: 3.1027x; 1.0651x over previous
#include <cuda_runtime.h>
#include <math.h>
#include <stdint.h>

#define NN 50000
#define EE 800000
#define HIDC 128
#define FFC 256
#define NLAYERS 6
#define EPSLN 1e-5f

// ---------------- scratch (device globals; no allocation allowed) ----------------
__device__ float g_z[NN * HIDC];
__device__ float g_q[NN * HIDC];
__device__ float g_k[NN * HIDC];
__device__ float g_v[NN * HIDC];
__device__ float g_sk[NN * HIDC];
__device__ float g_attn[NN * HIDC];
__device__ float g_h[NN * HIDC];
__device__ float g_t[NN * FFC];
__device__ float g_u[NN * HIDC];
__device__ int g_src[EE];
__device__ int g_dst[EE];
__device__ int g_deg[NN];
__device__ int g_rowptr[NN + 1];
__device__ int g_cur[NN];
__device__ int g_csrc[EE];
__device__ int g_csums[128];
__device__ float g_betas[NLAYERS + 2];
__device__ int g_flag[1];

// tf32-preconverted weights
#define OFF_WQ  16384
#define OFF_WK  (OFF_WQ + NLAYERS * HIDC * HIDC)
#define OFF_WV  (OFF_WK + NLAYERS * HIDC * HIDC)
#define OFF_WSK (OFF_WV + NLAYERS * HIDC * HIDC)
#define OFF_W1  (OFF_WSK + NLAYERS * HIDC * HIDC)
#define OFF_W2  (OFF_W1 + NLAYERS * HIDC * FFC)
#define TOTW    (OFF_W2 + NLAYERS * FFC * HIDC)
__device__ float g_wt[TOTW];

#define CHUNK 512
#define NCHK ((NN + CHUNK - 1) / CHUNK)   // 98

// ---------------- helpers ----------------
__device__ __forceinline__ uint32_t f2tf32(float x) {
    uint32_t r;
    asm("cvt.rna.tf32.f32 %0, %1;" : "=r"(r) : "f"(x));
    return r;
}

__device__ __forceinline__ void mma_tf32(float* d, const uint32_t* a, const uint32_t* b) {
    asm volatile(
        "mma.sync.aligned.m16n8k8.row.col.f32.tf32.tf32.f32 "
        "{%0,%1,%2,%3}, {%4,%5,%6,%7}, {%8,%9}, {%0,%1,%2,%3};"
        : "+f"(d[0]), "+f"(d[1]), "+f"(d[2]), "+f"(d[3])
        : "r"(a[0]), "r"(a[1]), "r"(a[2]), "r"(a[3]), "r"(b[0]), "r"(b[1]));
}

__device__ __forceinline__ void cp16(uint32_t saddr, const void* g) {
    asm volatile("cp.async.ca.shared.global [%0], [%1], 16;" ::"r"(saddr), "l"(g));
}
__device__ __forceinline__ void cp_commit() {
    asm volatile("cp.async.commit_group;");
}
__device__ __forceinline__ void cp_wait0() {
    asm volatile("cp.async.wait_group 0;");
}

// ---------------- edge index dtype sniff + convert ----------------
__global__ void sniff_kernel(const unsigned* __restrict__ w) {
    if (threadIdx.x == 0 && blockIdx.x == 0) {
        int is64 = 1;
        for (int i = 1; i < 64; i += 2)
            if (w[i] != 0u) { is64 = 0; break; }
        g_flag[0] = is64;
    }
}

__global__ __launch_bounds__(256) void convert_edges(const void* __restrict__ ei) {
    int e = blockIdx.x * blockDim.x + threadIdx.x;
    if (e >= EE) return;
    if (g_flag[0]) {
        const long long* p = (const long long*)ei;
        g_src[e] = (int)p[e];
        g_dst[e] = (int)p[EE + e];
    } else {
        const int* p = (const int*)ei;
        g_src[e] = p[e];
        g_dst[e] = p[EE + e];
    }
}

__global__ void beta_softmax(const float* __restrict__ beta) {
    if (threadIdx.x == 0 && blockIdx.x == 0) {
        float m = -1e30f;
        for (int i = 0; i < NLAYERS + 1; i++) m = fmaxf(m, beta[i]);
        float s = 0.f;
        for (int i = 0; i < NLAYERS + 1; i++) {
            float e = expf(beta[i] - m);
            g_betas[i] = e;
            s += e;
        }
        for (int i = 0; i < NLAYERS + 1; i++) g_betas[i] /= s;
    }
}

// ---------------- one-shot weight tf32 preconversion ----------------
__global__ __launch_bounds__(256) void convW(
    const float* __restrict__ Win, const float* __restrict__ Wq,
    const float* __restrict__ Wk, const float* __restrict__ Wv,
    const float* __restrict__ Wsk, const float* __restrict__ W1,
    const float* __restrict__ W2) {
    int i = blockIdx.x * blockDim.x + threadIdx.x;
    if (i >= TOTW) return;
    const float* src;
    int off;
    if (i < OFF_WQ)       { src = Win; off = i; }
    else if (i < OFF_WK)  { src = Wq;  off = i - OFF_WQ; }
    else if (i < OFF_WV)  { src = Wk;  off = i - OFF_WK; }
    else if (i < OFF_WSK) { src = Wv;  off = i - OFF_WV; }
    else if (i < OFF_W1)  { src = Wsk; off = i - OFF_WSK; }
    else if (i < OFF_W2)  { src = W1;  off = i - OFF_W1; }
    else                  { src = W2;  off = i - OFF_W2; }
    g_wt[i] = __uint_as_float(f2tf32(src[off]));
}

// ---------------- CSR build ----------------
__global__ __launch_bounds__(256) void k_clear_deg() {
    int i = blockIdx.x * blockDim.x + threadIdx.x;
    if (i < NN) g_deg[i] = 0;
}
__global__ __launch_bounds__(256) void k_hist() {
    int e = blockIdx.x * blockDim.x + threadIdx.x;
    if (e < EE) atomicAdd(&g_deg[g_dst[e]], 1);
}
__global__ __launch_bounds__(CHUNK) void k_chunksum() {
    __shared__ int sh[CHUNK];
    int tid = threadIdx.x;
    int i = blockIdx.x * CHUNK + tid;
    sh[tid] = (i < NN) ? g_deg[i] : 0;
    __syncthreads();
    for (int off = CHUNK / 2; off > 0; off >>= 1) {
        if (tid < off) sh[tid] += sh[tid + off];
        __syncthreads();
    }
    if (tid == 0) g_csums[blockIdx.x] = sh[0];
}
__global__ void k_scanchunks() {
    if (threadIdx.x == 0 && blockIdx.x == 0) {
        int run = 0;
        for (int c = 0; c < NCHK; c++) {
            int v = g_csums[c];
            g_csums[c] = run;
            run += v;
        }
        g_rowptr[NN] = run;
    }
}
__global__ __launch_bounds__(CHUNK) void k_rowptr() {
    __shared__ int sh[CHUNK];
    int tid = threadIdx.x;
    int i = blockIdx.x * CHUNK + tid;
    int v = (i < NN) ? g_deg[i] : 0;
    sh[tid] = v;
    __syncthreads();
    for (int off = 1; off < CHUNK; off <<= 1) {
        int t = (tid >= off) ? sh[tid - off] : 0;
        __syncthreads();
        sh[tid] += t;
        __syncthreads();
    }
    if (i < NN) {
        int excl = sh[tid] - v + g_csums[blockIdx.x];
        g_rowptr[i] = excl;
        g_cur[i] = excl;
    }
}
__global__ __launch_bounds__(256) void k_fill() {
    int e = blockIdx.x * blockDim.x + threadIdx.x;
    if (e >= EE) return;
    int slot = atomicAdd(&g_cur[g_dst[e]], 1);
    g_csrc[slot] = g_src[e];
}

// ---------------- TF32 GEMM: 256 thr, 8 warps (2x4), warp tile 64x32 ----------
// B operand is pre-converted tf32 (g_wt) staged via cp.async.
// __launch_bounds__(256,2) caps regs at 128 -> 2 blocks/SM (16 warps).
#define BM 128
#define BN 128
#define BK 16

__device__ __forceinline__ void ldA(
    const float* __restrict__ A, int M, int K, int m0, int kc, int tid,
    float4 ar[2]) {
#pragma unroll
    for (int i = 0; i < 2; i++) {
        int f = tid + i * 256;
        int m = f >> 2, k4 = (f & 3) * 4;
        ar[i] = (m0 + m < M)
                    ? *(const float4*)(A + (size_t)(m0 + m) * K + kc + k4)
                    : make_float4(0.f, 0.f, 0.f, 0.f);
    }
}

__device__ __forceinline__ void stA(float (*As)[BK + 4], int tid,
                                    const float4 ar[2]) {
#pragma unroll
    for (int i = 0; i < 2; i++) {
        int f = tid + i * 256;
        int m = f >> 2, k4 = (f & 3) * 4;
        float4 cv;
        cv.x = __uint_as_float(f2tf32(ar[i].x));
        cv.y = __uint_as_float(f2tf32(ar[i].y));
        cv.z = __uint_as_float(f2tf32(ar[i].z));
        cv.w = __uint_as_float(f2tf32(ar[i].w));
        *(float4*)&As[m][k4] = cv;
    }
}

__device__ __forceinline__ void cpB(float (*Bs)[BN + 8],
                                    const float* __restrict__ B, int Nld,
                                    int n0, int kc, int tid) {
#pragma unroll
    for (int i = 0; i < 2; i++) {
        int f = tid + i * 256;
        int k = f >> 5, n4 = (f & 31) * 4;
        uint32_t sa = (uint32_t)__cvta_generic_to_shared(&Bs[k][n4]);
        cp16(sa, B + (size_t)(kc + k) * Nld + n0 + n4);
    }
}

template <int ACT>
__device__ __forceinline__ void gemm_core(
    const float* __restrict__ A, const float* __restrict__ B,
    const float* __restrict__ bias, float* __restrict__ C,
    int M, int K, int Nld, int m0, int n0,
    float As[2][BM][BK + 4], float Bs[2][BK][BN + 8]) {
    int tid = threadIdx.x;
    int warp = tid >> 5, lane = tid & 31;
    int wm = (warp >> 2) * 64, wn = (warp & 3) * 32;
    int g = lane >> 2, t = lane & 3;

    float acc[4][4][4];
#pragma unroll
    for (int a = 0; a < 4; a++)
#pragma unroll
        for (int b = 0; b < 4; b++)
#pragma unroll
            for (int c = 0; c < 4; c++) acc[a][b][c] = 0.f;

    float4 ar[2];
    ldA(A, M, K, m0, 0, tid, ar);
    cpB(Bs[0], B, Nld, n0, 0, tid);
    stA(As[0], tid, ar);
    cp_commit();
    cp_wait0();
    __syncthreads();

    int nit = K / BK;
    for (int it = 0; it < nit; it++) {
        int cur = it & 1;
        if (it + 1 < nit) {
            ldA(A, M, K, m0, (it + 1) * BK, tid, ar);
            cpB(Bs[cur ^ 1], B, Nld, n0, (it + 1) * BK, tid);
            cp_commit();
        }

#pragma unroll
        for (int kk = 0; kk < BK; kk += 8) {
            uint32_t af[4][4];
#pragma unroll
            for (int tm = 0; tm < 4; tm++) {
                int mb = wm + tm * 16;
                af[tm][0] = __float_as_uint(As[cur][mb + g][kk + t]);
                af[tm][1] = __float_as_uint(As[cur][mb + g + 8][kk + t]);
                af[tm][2] = __float_as_uint(As[cur][mb + g][kk + t + 4]);
                af[tm][3] = __float_as_uint(As[cur][mb + g + 8][kk + t + 4]);
            }
            uint32_t bf[4][2];
#pragma unroll
            for (int tn = 0; tn < 4; tn++) {
                int nb = wn + tn * 8;
                bf[tn][0] = __float_as_uint(Bs[cur][kk + t][nb + g]);
                bf[tn][1] = __float_as_uint(Bs[cur][kk + t + 4][nb + g]);
            }
#pragma unroll
            for (int tm = 0; tm < 4; tm++)
#pragma unroll
                for (int tn = 0; tn < 4; tn++)
                    mma_tf32(acc[tm][tn], af[tm], bf[tn]);
        }

        if (it + 1 < nit) stA(As[cur ^ 1], tid, ar);
        cp_wait0();
        __syncthreads();
    }

    // epilogue: c0,c1 row g cols 2t,2t+1 ; c2,c3 row g+8
#pragma unroll
    for (int tm = 0; tm < 4; tm++) {
        int r0 = m0 + wm + tm * 16 + g;
        int r1 = r0 + 8;
#pragma unroll
        for (int tn = 0; tn < 4; tn++) {
            int cb = n0 + wn + tn * 8 + 2 * t;
            float b0 = __ldg(bias + cb);
            float b1 = __ldg(bias + cb + 1);
            float v00 = acc[tm][tn][0] + b0;
            float v01 = acc[tm][tn][1] + b1;
            float v10 = acc[tm][tn][2] + b0;
            float v11 = acc[tm][tn][3] + b1;
            if (ACT == 1) {
                v00 = fmaxf(v00, 0.f); v01 = fmaxf(v01, 0.f);
                v10 = fmaxf(v10, 0.f); v11 = fmaxf(v11, 0.f);
            }
            if (ACT == 2) {
                v00 = 0.5f * v00 * (1.f + erff(v00 * 0.70710678118654752f));
                v01 = 0.5f * v01 * (1.f + erff(v01 * 0.70710678118654752f));
                v10 = 0.5f * v10 * (1.f + erff(v10 * 0.70710678118654752f));
                v11 = 0.5f * v11 * (1.f + erff(v11 * 0.70710678118654752f));
            }
            if (r0 < M) *(float2*)(C + (size_t)r0 * Nld + cb) = make_float2(v00, v01);
            if (r1 < M) *(float2*)(C + (size_t)r1 * Nld + cb) = make_float2(v10, v11);
        }
    }
}

template <int ACT>
__global__ __launch_bounds__(256, 2) void gemm_tf32(
    const float* __restrict__ A, const float* __restrict__ B,
    const float* __restrict__ bias, float* __restrict__ C,
    int M, int K, int Nld) {
    __shared__ __align__(16) float As[2][BM][BK + 4];
    __shared__ __align__(16) float Bs[2][BK][BN + 8];
    gemm_core<ACT>(A, B, bias, C, M, K, Nld, blockIdx.x * BM, blockIdx.y * BN,
                   As, Bs);
}

// fused Q/K/V/SK projection: grid.y in [0,4) selects operator
__global__ __launch_bounds__(256, 2) void gemm_qkvsk(
    const float* __restrict__ A, const float* __restrict__ wt,
    const float* __restrict__ bq, const float* __restrict__ bk,
    const float* __restrict__ bv, const float* __restrict__ bsk, int l) {
    __shared__ __align__(16) float As[2][BM][BK + 4];
    __shared__ __align__(16) float Bs[2][BK][BN + 8];
    const float* B;
    const float* bias;
    float* C;
    switch (blockIdx.y) {
        case 0: B = wt + OFF_WQ;  bias = bq;  C = g_q;  break;
        case 1: B = wt + OFF_WK;  bias = bk;  C = g_k;  break;
        case 2: B = wt + OFF_WV;  bias = bv;  C = g_v;  break;
        default: B = wt + OFF_WSK; bias = bsk; C = g_sk; break;
    }
    B += (size_t)l * HIDC * HIDC;
    bias += l * HIDC;
    gemm_core<0>(A, B, bias, C, NN, HIDC, HIDC, blockIdx.x * BM, 0, As, Bs);
}

// ---------------- fused attention: warp/node, online softmax, 2-edge unroll ----
__global__ __launch_bounds__(256) void attn_fused() {
    int node = (blockIdx.x * blockDim.x + threadIdx.x) >> 5;
    if (node >= NN) return;
    int lane = threadIdx.x & 31;
    int beg = g_rowptr[node], end = g_rowptr[node + 1];
    size_t qb = (size_t)node * HIDC + lane * 4;
    float4 qv = *(const float4*)(g_q + qb);
    float m = -INFINITY, l = 0.f;
    float4 acc = make_float4(0.f, 0.f, 0.f, 0.f);
    int e = beg;
    for (; e + 1 < end; e += 2) {
        int s0 = g_csrc[e], s1 = g_csrc[e + 1];
        size_t b0 = (size_t)s0 * HIDC + lane * 4;
        size_t b1 = (size_t)s1 * HIDC + lane * 4;
        float4 k0 = *(const float4*)(g_k + b0);
        float4 k1 = *(const float4*)(g_k + b1);
        float4 v0 = *(const float4*)(g_v + b0);
        float4 v1 = *(const float4*)(g_v + b1);
        float p0 = qv.x * k0.x + qv.y * k0.y + qv.z * k0.z + qv.w * k0.w;
        float p1 = qv.x * k1.x + qv.y * k1.y + qv.z * k1.z + qv.w * k1.w;
        p0 += __shfl_xor_sync(0xffffffffu, p0, 8, 16);
        p1 += __shfl_xor_sync(0xffffffffu, p1, 8, 16);
        p0 += __shfl_xor_sync(0xffffffffu, p0, 4, 16);
        p1 += __shfl_xor_sync(0xffffffffu, p1, 4, 16);
        p0 += __shfl_xor_sync(0xffffffffu, p0, 2, 16);
        p1 += __shfl_xor_sync(0xffffffffu, p1, 2, 16);
        p0 += __shfl_xor_sync(0xffffffffu, p0, 1, 16);
        p1 += __shfl_xor_sync(0xffffffffu, p1, 1, 16);
        float sc0 = p0 * 0.125f;
        float sc1 = p1 * 0.125f;
        float mn = fmaxf(m, fmaxf(sc0, sc1));
        float scale = __expf(m - mn);
        float w0 = __expf(sc0 - mn);
        float w1 = __expf(sc1 - mn);
        l = l * scale + w0 + w1;
        acc.x = acc.x * scale + w0 * v0.x + w1 * v1.x;
        acc.y = acc.y * scale + w0 * v0.y + w1 * v1.y;
        acc.z = acc.z * scale + w0 * v0.z + w1 * v1.z;
        acc.w = acc.w * scale + w0 * v0.w + w1 * v1.w;
        m = mn;
    }
    if (e < end) {
        int s = g_csrc[e];
        size_t sb = (size_t)s * HIDC + lane * 4;
        float4 kv = *(const float4*)(g_k + sb);
        float4 vv = *(const float4*)(g_v + sb);
        float p = qv.x * kv.x + qv.y * kv.y + qv.z * kv.z + qv.w * kv.w;
        p += __shfl_xor_sync(0xffffffffu, p, 8, 16);
        p += __shfl_xor_sync(0xffffffffu, p, 4, 16);
        p += __shfl_xor_sync(0xffffffffu, p, 2, 16);
        p += __shfl_xor_sync(0xffffffffu, p, 1, 16);
        float sc = p * 0.125f;
        float mn = fmaxf(m, sc);
        float scale = __expf(m - mn);
        float w = __expf(sc - mn);
        l = l * scale + w;
        acc.x = acc.x * scale + w * vv.x;
        acc.y = acc.y * scale + w * vv.y;
        acc.z = acc.z * scale + w * vv.z;
        acc.w = acc.w * scale + w * vv.w;
    }
    float inv = (l > 0.f) ? 1.f / l : 0.f;
    acc.x *= inv; acc.y *= inv; acc.z *= inv; acc.w *= inv;
    *(float4*)(g_attn + qb) = acc;
}

// ---------------- layernorm kernels (warp per row, 128 cols) ----------------
__global__ __launch_bounds__(256) void ln3_kernel(
    const float* __restrict__ g, const float* __restrict__ bt) {
    int row = (blockIdx.x * blockDim.x + threadIdx.x) >> 5;
    if (row >= NN) return;
    int lane = threadIdx.x & 31;
    size_t base = (size_t)row * HIDC + lane * 4;
    float4 a = *(const float4*)(g_z + base);
    float4 b = *(const float4*)(g_attn + base);
    float4 c = *(const float4*)(g_sk + base);
    float v0 = a.x + b.x + c.x, v1 = a.y + b.y + c.y;
    float v2 = a.z + b.z + c.z, v3 = a.w + b.w + c.w;
    float s = v0 + v1 + v2 + v3;
#pragma unroll
    for (int o = 16; o > 0; o >>= 1) s += __shfl_xor_sync(0xffffffffu, s, o);
    float mu = s * (1.f / HIDC);
    float d0 = v0 - mu, d1 = v1 - mu, d2 = v2 - mu, d3 = v3 - mu;
    float ss = d0 * d0 + d1 * d1 + d2 * d2 + d3 * d3;
#pragma unroll
    for (int o = 16; o > 0; o >>= 1) ss += __shfl_xor_sync(0xffffffffu, ss, o);
    float rs = rsqrtf(ss * (1.f / HIDC) + EPSLN);
    int col = lane * 4;
    float4 o4;
    o4.x = d0 * rs * g[col + 0] + bt[col + 0];
    o4.y = d1 * rs * g[col + 1] + bt[col + 1];
    o4.z = d2 * rs * g[col + 2] + bt[col + 2];
    o4.w = d3 * rs * g[col + 3] + bt[col + 3];
    *(float4*)(g_h + base) = o4;
}

// z = relu(LN(h+u)); out += betas[li]*z
__global__ __launch_bounds__(256) void lnacc_kernel(
    const float* __restrict__ g, const float* __restrict__ bt,
    float* __restrict__ out, int li) {
    int row = (blockIdx.x * blockDim.x + threadIdx.x) >> 5;
    if (row >= NN) return;
    int lane = threadIdx.x & 31;
    size_t base = (size_t)row * HIDC + lane * 4;
    float4 a = *(const float4*)(g_h + base);
    float4 b = *(const float4*)(g_u + base);
    float v0 = a.x + b.x, v1 = a.y + b.y, v2 = a.z + b.z, v3 = a.w + b.w;
    float s = v0 + v1 + v2 + v3;
#pragma unroll
    for (int o = 16; o > 0; o >>= 1) s += __shfl_xor_sync(0xffffffffu, s, o);
    float mu = s * (1.f / HIDC);
    float d0 = v0 - mu, d1 = v1 - mu, d2 = v2 - mu, d3 = v3 - mu;
    float ss = d0 * d0 + d1 * d1 + d2 * d2 + d3 * d3;
#pragma unroll
    for (int o = 16; o > 0; o >>= 1) ss += __shfl_xor_sync(0xffffffffu, ss, o);
    float rs = rsqrtf(ss * (1.f / HIDC) + EPSLN);
    int col = lane * 4;
    float z0 = fmaxf(d0 * rs * g[col + 0] + bt[col + 0], 0.f);
    float z1 = fmaxf(d1 * rs * g[col + 1] + bt[col + 1], 0.f);
    float z2 = fmaxf(d2 * rs * g[col + 2] + bt[col + 2], 0.f);
    float z3 = fmaxf(d3 * rs * g[col + 3] + bt[col + 3], 0.f);
    float bb = g_betas[li];
    *(float4*)(g_z + base) = make_float4(z0, z1, z2, z3);
    float4 oo = *(float4*)(out + base);
    oo.x += bb * z0; oo.y += bb * z1; oo.z += bb * z2; oo.w += bb * z3;
    *(float4*)(out + base) = oo;
}

__global__ __launch_bounds__(256) void init_acc(float* __restrict__ out) {
    int i = blockIdx.x * blockDim.x + threadIdx.x;
    if (i < NN * HIDC) out[i] = g_betas[0] * g_z[i];
}

// ---------------- host launcher ----------------
extern "C" void kernel_launch(void* const* d_in, const int* in_sizes, int n_in,
                              void* d_out, int out_size) {
    const float* x    = (const float*)d_in[0];
    const void*  ei   = d_in[1];
    const float* Win  = (const float*)d_in[2];
    const float* b_in = (const float*)d_in[3];
    const float* Wq   = (const float*)d_in[4];
    const float* bq   = (const float*)d_in[5];
    const float* Wk   = (const float*)d_in[6];
    const float* bk   = (const float*)d_in[7];
    const float* Wv   = (const float*)d_in[8];
    const float* bv   = (const float*)d_in[9];
    const float* Wsk  = (const float*)d_in[10];
    const float* bsk  = (const float*)d_in[11];
    const float* W1   = (const float*)d_in[12];
    const float* b1   = (const float*)d_in[13];
    const float* W2   = (const float*)d_in[14];
    const float* b2   = (const float*)d_in[15];
    const float* g1   = (const float*)d_in[16];
    const float* bt1  = (const float*)d_in[17];
    const float* g2   = (const float*)d_in[18];
    const float* bt2  = (const float*)d_in[19];
    const float* beta = (const float*)d_in[20];
    float* out = (float*)d_out;

    float *z, *h, *t, *u, *wt;
    cudaGetSymbolAddress((void**)&z, g_z);
    cudaGetSymbolAddress((void**)&h, g_h);
    cudaGetSymbolAddress((void**)&t, g_t);
    cudaGetSymbolAddress((void**)&u, g_u);
    cudaGetSymbolAddress((void**)&wt, g_wt);

    const int GM = (NN + BM - 1) / BM;  // 391

    // captures land on launch index 3 -> put a representative GEMM there
    sniff_kernel<<<1, 32>>>((const unsigned*)ei);                        // 0
    beta_softmax<<<1, 32>>>(beta);                                       // 1
    convW<<<(TOTW + 255) / 256, 256>>>(Win, Wq, Wk, Wv, Wsk, W1, W2);    // 2
    gemm_tf32<1><<<dim3(GM, 1), 256>>>(x, wt, b_in, z, NN, HIDC, HIDC);  // 3
    gemm_qkvsk<<<dim3(GM, 4), 256>>>(z, wt, bq, bk, bv, bsk, 0);         // 4

    init_acc<<<(NN * HIDC + 255) / 256, 256>>>(out);
    convert_edges<<<(EE + 255) / 256, 256>>>(ei);

    // CSR build (once; needed before first attn)
    k_clear_deg<<<(NN + 255) / 256, 256>>>();
    k_hist<<<(EE + 255) / 256, 256>>>();
    k_chunksum<<<NCHK, CHUNK>>>();
    k_scanchunks<<<1, 32>>>();
    k_rowptr<<<NCHK, CHUNK>>>();
    k_fill<<<(EE + 255) / 256, 256>>>();

    for (int l = 0; l < NLAYERS; l++) {
        if (l > 0)
            gemm_qkvsk<<<dim3(GM, 4), 256>>>(z, wt, bq, bk, bv, bsk, l);

        attn_fused<<<(NN * 32 + 255) / 256, 256>>>();

        ln3_kernel<<<(NN + 7) / 8, 256>>>(g1 + l * HIDC, bt1 + l * HIDC);

        gemm_tf32<2><<<dim3(GM, 2), 256>>>(h, wt + OFF_W1 + (size_t)l * HIDC * FFC,
                                           b1 + l * FFC, t, NN, HIDC, FFC);
        gemm_tf32<0><<<dim3(GM, 1), 256>>>(t, wt + OFF_W2 + (size_t)l * FFC * HIDC,
                                           b2 + l * HIDC, u, NN, FFC, HIDC);

        lnacc_kernel<<<(NN + 7) / 8, 256>>>(g2 + l * HIDC, bt2 + l * HIDC, out, l + 1);
    }
}